// round 4
// baseline (speedup 1.0000x reference)
#include <cuda_runtime.h>
#include <cuda_bf16.h>
#include <stdint.h>

#define N_NODES 20000
#define D_IN    128
#define D_H     256
#define LN_EPS  1e-5f

// ---------------- scratch (no dynamic allocation allowed) ----------------
__device__ float g_deg [N_NODES];
__device__ float g_dinv[N_NODES];
__device__ float g_h1  [N_NODES * D_H];  // x@W1, later h@W2
__device__ float g_agg [N_NODES * D_H];  // scatter accumulator (both hops)
__device__ float g_hres[N_NODES * D_H];  // x@Wres + bres
__device__ float g_h   [N_NODES * D_H];  // after LN1

// ---------------- helpers ----------------
__device__ __forceinline__ void red_add_v4(float4* addr, float4 v) {
    asm volatile("red.global.add.v4.f32 [%0], {%1,%2,%3,%4};"
                 :: "l"(addr), "f"(v.x), "f"(v.y), "f"(v.z), "f"(v.w)
                 : "memory");
}

// ---------------- init: deg = 1 (self loop), agg = 0 ----------------
__global__ void init_kernel() {
    int total = N_NODES * D_H;
    for (int i = blockIdx.x * blockDim.x + threadIdx.x; i < total;
         i += gridDim.x * blockDim.x) {
        g_agg[i] = 0.0f;
        if (i < N_NODES) g_deg[i] = 1.0f;
    }
}

// ---------------- degree accumulation over edges ----------------
__global__ void deg_kernel(const int* __restrict__ dst,
                           const float* __restrict__ w, int E) {
    for (int e = blockIdx.x * blockDim.x + threadIdx.x; e < E;
         e += gridDim.x * blockDim.x) {
        atomicAdd(&g_deg[dst[e]], w[e]);
    }
}

__global__ void dinv_kernel() {
    for (int i = blockIdx.x * blockDim.x + threadIdx.x; i < N_NODES;
         i += gridDim.x * blockDim.x) {
        float d = g_deg[i];
        g_dinv[i] = d > 0.0f ? rsqrtf(d) : 0.0f;
    }
}

// ---------------- fp32 GEMM: C[M,256] = A[M,K] @ B[K,256] (+bias) ----------
// BM=128 BN=128 BK=8, 256 threads, 8x8 per-thread microtile, float4 LDS.
template<int K, bool HAS_BIAS>
__global__ __launch_bounds__(256, 2)
void sgemm_kernel(const float* __restrict__ A,
                  const float* __restrict__ B,
                  const float* __restrict__ bias,
                  float* __restrict__ C, int M) {
    __shared__ float As[8][132];   // padded: kills transpose-store conflicts
    __shared__ float Bs[8][128];

    const int tid = threadIdx.x;
    const int tx  = tid & 15;          // 0..15 -> cols tx*8 .. tx*8+7
    const int ty  = tid >> 4;          // 0..15 -> rows ty*8 .. ty*8+7
    const int bm  = blockIdx.x * 128;
    const int bn  = blockIdx.y * 128;

    // A-load: row = tid/2 (0..127), k4 = (tid&1)*4
    const int a_row = tid >> 1;
    const int a_k   = (tid & 1) * 4;
    // B-load: krow = tid/32 (0..7), col4 = (tid&31)*4
    const int b_kr  = tid >> 5;
    const int b_c   = (tid & 31) * 4;

    float acc[8][8];
#pragma unroll
    for (int i = 0; i < 8; i++)
#pragma unroll
        for (int j = 0; j < 8; j++) acc[i][j] = 0.0f;

    const int gr = bm + a_row;

    // preload tile 0
    float4 av = make_float4(0.f, 0.f, 0.f, 0.f);
    if (gr < M) av = *reinterpret_cast<const float4*>(A + (long)gr * K + a_k);
    float4 bv = *reinterpret_cast<const float4*>(B + (long)b_kr * D_H + bn + b_c);
    As[a_k + 0][a_row] = av.x;
    As[a_k + 1][a_row] = av.y;
    As[a_k + 2][a_row] = av.z;
    As[a_k + 3][a_row] = av.w;
    *reinterpret_cast<float4*>(&Bs[b_kr][b_c]) = bv;
    __syncthreads();

    for (int kt = 8; kt <= K; kt += 8) {
        // prefetch next tile into registers
        if (kt < K) {
            av = make_float4(0.f, 0.f, 0.f, 0.f);
            if (gr < M)
                av = *reinterpret_cast<const float4*>(A + (long)gr * K + kt + a_k);
            bv = *reinterpret_cast<const float4*>(B + (long)(kt + b_kr) * D_H + bn + b_c);
        }
        // compute current tile
#pragma unroll
        for (int k = 0; k < 8; k++) {
            float4 a0 = *reinterpret_cast<const float4*>(&As[k][ty * 8]);
            float4 a1 = *reinterpret_cast<const float4*>(&As[k][ty * 8 + 4]);
            float4 b0 = *reinterpret_cast<const float4*>(&Bs[k][tx * 8]);
            float4 b1 = *reinterpret_cast<const float4*>(&Bs[k][tx * 8 + 4]);
            float a[8] = {a0.x, a0.y, a0.z, a0.w, a1.x, a1.y, a1.z, a1.w};
            float b[8] = {b0.x, b0.y, b0.z, b0.w, b1.x, b1.y, b1.z, b1.w};
#pragma unroll
            for (int i = 0; i < 8; i++)
#pragma unroll
                for (int j = 0; j < 8; j++) acc[i][j] += a[i] * b[j];
        }
        if (kt < K) {
            __syncthreads();
            As[a_k + 0][a_row] = av.x;
            As[a_k + 1][a_row] = av.y;
            As[a_k + 2][a_row] = av.z;
            As[a_k + 3][a_row] = av.w;
            *reinterpret_cast<float4*>(&Bs[b_kr][b_c]) = bv;
            __syncthreads();
        }
    }

    float bb[8];
#pragma unroll
    for (int j = 0; j < 8; j++)
        bb[j] = HAS_BIAS ? bias[bn + tx * 8 + j] : 0.0f;

#pragma unroll
    for (int i = 0; i < 8; i++) {
        int row = bm + ty * 8 + i;
        if (row < M) {
            float4 o0 = make_float4(acc[i][0] + bb[0], acc[i][1] + bb[1],
                                    acc[i][2] + bb[2], acc[i][3] + bb[3]);
            float4 o1 = make_float4(acc[i][4] + bb[4], acc[i][5] + bb[5],
                                    acc[i][6] + bb[6], acc[i][7] + bb[7]);
            float* cp = C + (long)row * D_H + bn + tx * 8;
            *reinterpret_cast<float4*>(cp)     = o0;
            *reinterpret_cast<float4*>(cp + 4) = o1;
        }
    }
}

// ---------------- edge scatter: agg[dst] += norm * feat[src] ----------------
// one warp per edge; 64 float4 per row -> 2 per lane; vector red (no return)
__global__ void scatter_kernel(const int* __restrict__ src,
                               const int* __restrict__ dst,
                               const float* __restrict__ w,
                               const float* __restrict__ feat,
                               int E) {
    int gw = (blockIdx.x * blockDim.x + threadIdx.x) >> 5;
    int lane = threadIdx.x & 31;
    int nw = (gridDim.x * blockDim.x) >> 5;
    for (int e = gw; e < E; e += nw) {
        int s = src[e];
        int d = dst[e];
        float n = g_dinv[s] * w[e] * g_dinv[d];
        const float4* fs = reinterpret_cast<const float4*>(feat + (long)s * D_H);
        float4* fd = reinterpret_cast<float4*>(g_agg + (long)d * D_H);
#pragma unroll
        for (int i = 0; i < 2; i++) {
            float4 v = fs[lane + i * 32];
            red_add_v4(&fd[lane + i * 32],
                       make_float4(v.x * n, v.y * n, v.z * n, v.w * n));
        }
    }
}

// ---------------- block-wide mean/var helper ----------------
__device__ __forceinline__ void block_stats(float t, float& mu, float& var) {
    float s = t, sq = t * t;
#pragma unroll
    for (int o = 16; o; o >>= 1) {
        s  += __shfl_xor_sync(0xFFFFFFFFu, s, o);
        sq += __shfl_xor_sync(0xFFFFFFFFu, sq, o);
    }
    __shared__ float ss[8], ssq[8];
    int wid = threadIdx.x >> 5;
    if ((threadIdx.x & 31) == 0) { ss[wid] = s; ssq[wid] = sq; }
    __syncthreads();
    float ts = 0.f, tq = 0.f;
#pragma unroll
    for (int i = 0; i < 8; i++) { ts += ss[i]; tq += ssq[i]; }
    mu = ts * (1.0f / D_H);
    var = tq * (1.0f / D_H) - mu * mu;
}

// ---------------- LN1: h = LN(hres + relu(agg + dinv^2*h1 + b1)) ------------
// also re-zeros agg for hop 1
__global__ void ln1_kernel(const float* __restrict__ b1,
                           const float* __restrict__ gamma,
                           const float* __restrict__ beta) {
    int row = blockIdx.x;
    int c = threadIdx.x;
    long idx = (long)row * D_H + c;
    float di = g_dinv[row];
    float a = g_agg[idx] + di * di * g_h1[idx] + b1[c];
    g_agg[idx] = 0.0f;                      // reset for hop 1
    float t = g_hres[idx] + fmaxf(a, 0.0f);
    float mu, var;
    block_stats(t, mu, var);
    g_h[idx] = (t - mu) * rsqrtf(var + LN_EPS) * gamma[c] + beta[c];
}

// ---------------- LN2: out = LN(h + agg + dinv^2*h2 + b2) -------------------
__global__ void ln2_kernel(const float* __restrict__ b2,
                           const float* __restrict__ gamma,
                           const float* __restrict__ beta,
                           float* __restrict__ out) {
    int row = blockIdx.x;
    int c = threadIdx.x;
    long idx = (long)row * D_H + c;
    float di = g_dinv[row];
    float t = g_h[idx] + g_agg[idx] + di * di * g_h1[idx] + b2[c];
    float mu, var;
    block_stats(t, mu, var);
    out[idx] = (t - mu) * rsqrtf(var + LN_EPS) * gamma[c] + beta[c];
}

// ---------------- launch ----------------
extern "C" void kernel_launch(void* const* d_in, const int* in_sizes, int n_in,
                              void* d_out, int out_size) {
    const float* x      = (const float*)d_in[0];   // [20000,128]
    const int*   ei     = (const int*)d_in[1];     // [2,E] int32
    const float* ew     = (const float*)d_in[2];   // [E]
    const float* W1     = (const float*)d_in[3];
    const float* b1     = (const float*)d_in[4];
    const float* W2     = (const float*)d_in[5];
    const float* b2     = (const float*)d_in[6];
    const float* Wres   = (const float*)d_in[7];
    const float* bres   = (const float*)d_in[8];
    const float* gamma1 = (const float*)d_in[9];
    const float* beta1  = (const float*)d_in[10];
    const float* gamma2 = (const float*)d_in[11];
    const float* beta2  = (const float*)d_in[12];
    float* out = (float*)d_out;

    const int E = in_sizes[2];        // edge_weight element count
    const int* src = ei;
    const int* dst = ei + E;

    // TRUE device addresses of the scratch symbols (host-side name is the
    // host shadow; ATS would silently read host memory).
    float *p_h1 = nullptr, *p_hres = nullptr, *p_h = nullptr;
    cudaGetSymbolAddress((void**)&p_h1,   g_h1);
    cudaGetSymbolAddress((void**)&p_hres, g_hres);
    cudaGetSymbolAddress((void**)&p_h,    g_h);

    init_kernel<<<1024, 256>>>();
    deg_kernel<<<(E + 255) / 256, 256>>>(dst, ew, E);
    dinv_kernel<<<(N_NODES + 255) / 256, 256>>>();

    dim3 gemm_grid((N_NODES + 127) / 128, D_H / 128);
    // h1 = x @ W1 ; hres = x @ Wres + bres
    sgemm_kernel<D_IN, false><<<gemm_grid, 256>>>(x, W1, nullptr, p_h1, N_NODES);
    sgemm_kernel<D_IN, true ><<<gemm_grid, 256>>>(x, Wres, bres, p_hres, N_NODES);

    scatter_kernel<<<2048, 256>>>(src, dst, ew, p_h1, E);
    ln1_kernel<<<N_NODES, D_H>>>(b1, gamma1, beta1);

    // h2 = h @ W2  (reuse g_h1)
    sgemm_kernel<D_H, false><<<gemm_grid, 256>>>(p_h, W2, nullptr, p_h1, N_NODES);
    scatter_kernel<<<2048, 256>>>(src, dst, ew, p_h1, E);
    ln2_kernel<<<N_NODES, D_H>>>(b2, gamma2, beta2, out);
}

// round 5
// speedup vs baseline: 1.3409x; 1.3409x over previous
#include <cuda_runtime.h>
#include <cuda_bf16.h>
#include <stdint.h>

#define N_NODES 20000
#define D_IN    128
#define D_H     256
#define LN_EPS  1e-5f

// ---------------- scratch (no dynamic allocation allowed) ----------------
__device__ float g_deg [N_NODES];
__device__ float g_dinv[N_NODES];
__device__ float g_h1  [N_NODES * D_H];  // x@W1, later h@W2
__device__ float g_agg [N_NODES * D_H];  // scatter accumulator (both hops)
__device__ float g_hres[N_NODES * D_H];  // x@Wres + bres
__device__ float g_h   [N_NODES * D_H];  // after LN1

// ---------------- helpers ----------------
__device__ __forceinline__ void red_add_v4(float4* addr, float4 v) {
    asm volatile("red.global.add.v4.f32 [%0], {%1,%2,%3,%4};"
                 :: "l"(addr), "f"(v.x), "f"(v.y), "f"(v.z), "f"(v.w)
                 : "memory");
}

__device__ __forceinline__ uint32_t f2tf32(float f) {
    uint32_t u;
    asm("cvt.rna.tf32.f32 %0, %1;" : "=r"(u) : "f"(f));
    return u;
}

__device__ __forceinline__ void mma_tf32(float* c, const uint32_t* a, const uint32_t* b) {
    asm volatile(
        "mma.sync.aligned.m16n8k8.row.col.f32.tf32.tf32.f32 "
        "{%0,%1,%2,%3}, {%4,%5,%6,%7}, {%8,%9}, {%0,%1,%2,%3};"
        : "+f"(c[0]), "+f"(c[1]), "+f"(c[2]), "+f"(c[3])
        : "r"(a[0]), "r"(a[1]), "r"(a[2]), "r"(a[3]), "r"(b[0]), "r"(b[1]));
}

// ---------------- init: deg = 1 (self loop), agg = 0 ----------------
__global__ void init_kernel() {
    int total = N_NODES * D_H;
    for (int i = blockIdx.x * blockDim.x + threadIdx.x; i < total;
         i += gridDim.x * blockDim.x) {
        g_agg[i] = 0.0f;
        if (i < N_NODES) g_deg[i] = 1.0f;
    }
}

// ---------------- degree accumulation over edges ----------------
__global__ void deg_kernel(const int* __restrict__ dst,
                           const float* __restrict__ w, int E) {
    for (int e = blockIdx.x * blockDim.x + threadIdx.x; e < E;
         e += gridDim.x * blockDim.x) {
        atomicAdd(&g_deg[dst[e]], w[e]);
    }
}

__global__ void dinv_kernel() {
    for (int i = blockIdx.x * blockDim.x + threadIdx.x; i < N_NODES;
         i += gridDim.x * blockDim.x) {
        float d = g_deg[i];
        g_dinv[i] = d > 0.0f ? rsqrtf(d) : 0.0f;
    }
}

// ---------------- TF32 tensor-core GEMM ----------------
// C[M,256] = A[M,K] @ B[K,256] (+bias), BM=128 BN=64 BK=16, 256 thr (8 warps).
// Warp grid 4x2 (warp tile 32x32), m16n8k8 mma, fp32 accumulate.
// Dual mode: grid.y in [0, 2*nb): by/nb selects (B1,bias1,C1) vs (B2,bias2,C2).
template<int K>
__global__ __launch_bounds__(256)
void tf32_gemm_kernel(const float* __restrict__ A, int M, int nb,
                      const float* __restrict__ Bm1, const float* __restrict__ bias1,
                      float* __restrict__ C1,
                      const float* __restrict__ Bm2, const float* __restrict__ bias2,
                      float* __restrict__ C2) {
    __shared__ float As[128][20];   // [m][k], stride 20 -> conflict-free frags
    __shared__ float Bs[16][72];    // [k][n], stride 72 -> conflict-free frags

    const int tid  = threadIdx.x;
    const int lane = tid & 31;
    const int wid  = tid >> 5;
    const int wm   = (wid & 3) * 32;   // warp m offset
    const int wn   = (wid >> 2) * 32;  // warp n offset
    const int g    = lane >> 2;        // 0..7
    const int tg   = lane & 3;         // 0..3

    const int bm  = blockIdx.x * 128;
    const int mat = blockIdx.y / nb;
    const int bn  = (blockIdx.y % nb) * 64;

    const float* Bw   = mat ? Bm2   : Bm1;
    const float* bias = mat ? bias2 : bias1;
    float*       C    = mat ? C2    : C1;

    // loader mapping
    const int a_row = tid >> 1;          // 0..127
    const int a_k   = (tid & 1) * 4;     // 0 or 4 (second f4 at +8)
    const int b_kr  = tid >> 4;          // 0..15
    const int b_c   = (tid & 15) * 4;    // 0..60
    const bool a_ok = (bm + a_row) < M;
    const long a_base = (long)(bm + a_row) * K;

    float acc[2][4][4];
#pragma unroll
    for (int mt = 0; mt < 2; mt++)
#pragma unroll
        for (int nt = 0; nt < 4; nt++)
#pragma unroll
            for (int i = 0; i < 4; i++) acc[mt][nt][i] = 0.0f;

    // preload tile 0
    float4 av0 = make_float4(0.f,0.f,0.f,0.f), av1 = av0;
    if (a_ok) {
        av0 = *reinterpret_cast<const float4*>(A + a_base + a_k);
        av1 = *reinterpret_cast<const float4*>(A + a_base + a_k + 8);
    }
    float4 bv = *reinterpret_cast<const float4*>(Bw + (long)b_kr * D_H + bn + b_c);

    const int T = K / 16;
    for (int t = 0; t < T; t++) {
        __syncthreads();   // previous tile's readers done
        As[a_row][a_k + 0] = av0.x; As[a_row][a_k + 1] = av0.y;
        As[a_row][a_k + 2] = av0.z; As[a_row][a_k + 3] = av0.w;
        As[a_row][a_k + 8] = av1.x; As[a_row][a_k + 9] = av1.y;
        As[a_row][a_k +10] = av1.z; As[a_row][a_k +11] = av1.w;
        *reinterpret_cast<float4*>(&Bs[b_kr][b_c]) = bv;
        __syncthreads();

        if (t + 1 < T) {   // prefetch next tile (overlaps mma block)
            int kt = (t + 1) * 16;
            av0 = make_float4(0.f,0.f,0.f,0.f); av1 = av0;
            if (a_ok) {
                av0 = *reinterpret_cast<const float4*>(A + a_base + kt + a_k);
                av1 = *reinterpret_cast<const float4*>(A + a_base + kt + a_k + 8);
            }
            bv = *reinterpret_cast<const float4*>(Bw + (long)(kt + b_kr) * D_H + bn + b_c);
        }

#pragma unroll
        for (int ks = 0; ks < 16; ks += 8) {
            uint32_t af[2][4], bf[4][2];
#pragma unroll
            for (int mt = 0; mt < 2; mt++) {
                int r0 = wm + mt * 16 + g;
                af[mt][0] = f2tf32(As[r0    ][ks + tg    ]);
                af[mt][1] = f2tf32(As[r0 + 8][ks + tg    ]);
                af[mt][2] = f2tf32(As[r0    ][ks + tg + 4]);
                af[mt][3] = f2tf32(As[r0 + 8][ks + tg + 4]);
            }
#pragma unroll
            for (int nt = 0; nt < 4; nt++) {
                int c0 = wn + nt * 8 + g;
                bf[nt][0] = f2tf32(Bs[ks + tg    ][c0]);
                bf[nt][1] = f2tf32(Bs[ks + tg + 4][c0]);
            }
#pragma unroll
            for (int mt = 0; mt < 2; mt++)
#pragma unroll
                for (int nt = 0; nt < 4; nt++)
                    mma_tf32(acc[mt][nt], af[mt], bf[nt]);
        }
    }

    // epilogue: c0/c1 -> (row, col..col+1), c2/c3 -> (row+8, col..col+1)
#pragma unroll
    for (int mt = 0; mt < 2; mt++) {
        int row = bm + wm + mt * 16 + g;
#pragma unroll
        for (int nt = 0; nt < 4; nt++) {
            int col = bn + wn + nt * 8 + tg * 2;
            float b0 = bias ? bias[col]     : 0.0f;
            float b1 = bias ? bias[col + 1] : 0.0f;
            if (row < M) {
                float2 o = make_float2(acc[mt][nt][0] + b0, acc[mt][nt][1] + b1);
                *reinterpret_cast<float2*>(C + (long)row * D_H + col) = o;
            }
            if (row + 8 < M) {
                float2 o = make_float2(acc[mt][nt][2] + b0, acc[mt][nt][3] + b1);
                *reinterpret_cast<float2*>(C + (long)(row + 8) * D_H + col) = o;
            }
        }
    }
}

// ---------------- edge scatter: agg[dst] += norm * feat[src] ----------------
__global__ void scatter_kernel(const int* __restrict__ src,
                               const int* __restrict__ dst,
                               const float* __restrict__ w,
                               const float* __restrict__ feat,
                               int E) {
    int gw = (blockIdx.x * blockDim.x + threadIdx.x) >> 5;
    int lane = threadIdx.x & 31;
    int nw = (gridDim.x * blockDim.x) >> 5;
    for (int e = gw; e < E; e += nw) {
        int s = src[e];
        int d = dst[e];
        float n = g_dinv[s] * w[e] * g_dinv[d];
        const float4* fs = reinterpret_cast<const float4*>(feat + (long)s * D_H);
        float4* fd = reinterpret_cast<float4*>(g_agg + (long)d * D_H);
#pragma unroll
        for (int i = 0; i < 2; i++) {
            float4 v = fs[lane + i * 32];
            red_add_v4(&fd[lane + i * 32],
                       make_float4(v.x * n, v.y * n, v.z * n, v.w * n));
        }
    }
}

// ---------------- block-wide mean/var helper ----------------
__device__ __forceinline__ void block_stats(float t, float& mu, float& var) {
    float s = t, sq = t * t;
#pragma unroll
    for (int o = 16; o; o >>= 1) {
        s  += __shfl_xor_sync(0xFFFFFFFFu, s, o);
        sq += __shfl_xor_sync(0xFFFFFFFFu, sq, o);
    }
    __shared__ float ss[8], ssq[8];
    int wid = threadIdx.x >> 5;
    if ((threadIdx.x & 31) == 0) { ss[wid] = s; ssq[wid] = sq; }
    __syncthreads();
    float ts = 0.f, tq = 0.f;
#pragma unroll
    for (int i = 0; i < 8; i++) { ts += ss[i]; tq += ssq[i]; }
    mu = ts * (1.0f / D_H);
    var = tq * (1.0f / D_H) - mu * mu;
}

// ---------------- LN1: h = LN(hres + relu(agg + dinv^2*h1 + b1)) ------------
__global__ void ln1_kernel(const float* __restrict__ b1,
                           const float* __restrict__ gamma,
                           const float* __restrict__ beta) {
    int row = blockIdx.x;
    int c = threadIdx.x;
    long idx = (long)row * D_H + c;
    float di = g_dinv[row];
    float a = g_agg[idx] + di * di * g_h1[idx] + b1[c];
    g_agg[idx] = 0.0f;                      // reset for hop 1
    float t = g_hres[idx] + fmaxf(a, 0.0f);
    float mu, var;
    block_stats(t, mu, var);
    g_h[idx] = (t - mu) * rsqrtf(var + LN_EPS) * gamma[c] + beta[c];
}

// ---------------- LN2: out = LN(h + agg + dinv^2*h2 + b2) -------------------
__global__ void ln2_kernel(const float* __restrict__ b2,
                           const float* __restrict__ gamma,
                           const float* __restrict__ beta,
                           float* __restrict__ out) {
    int row = blockIdx.x;
    int c = threadIdx.x;
    long idx = (long)row * D_H + c;
    float di = g_dinv[row];
    float t = g_h[idx] + g_agg[idx] + di * di * g_h1[idx] + b2[c];
    float mu, var;
    block_stats(t, mu, var);
    out[idx] = (t - mu) * rsqrtf(var + LN_EPS) * gamma[c] + beta[c];
}

// ---------------- launch ----------------
extern "C" void kernel_launch(void* const* d_in, const int* in_sizes, int n_in,
                              void* d_out, int out_size) {
    const float* x      = (const float*)d_in[0];   // [20000,128]
    const int*   ei     = (const int*)d_in[1];     // [2,E] int32
    const float* ew     = (const float*)d_in[2];   // [E]
    const float* W1     = (const float*)d_in[3];
    const float* b1     = (const float*)d_in[4];
    const float* W2     = (const float*)d_in[5];
    const float* b2     = (const float*)d_in[6];
    const float* Wres   = (const float*)d_in[7];
    const float* bres   = (const float*)d_in[8];
    const float* gamma1 = (const float*)d_in[9];
    const float* beta1  = (const float*)d_in[10];
    const float* gamma2 = (const float*)d_in[11];
    const float* beta2  = (const float*)d_in[12];
    float* out = (float*)d_out;

    const int E = in_sizes[2];
    const int* src = ei;
    const int* dst = ei + E;

    // TRUE device addresses of scratch symbols (host name = host shadow).
    float *p_h1 = nullptr, *p_hres = nullptr, *p_h = nullptr;
    cudaGetSymbolAddress((void**)&p_h1,   g_h1);
    cudaGetSymbolAddress((void**)&p_hres, g_hres);
    cudaGetSymbolAddress((void**)&p_h,    g_h);

    init_kernel<<<1024, 256>>>();
    deg_kernel<<<(E + 255) / 256, 256>>>(dst, ew, E);
    dinv_kernel<<<(N_NODES + 255) / 256, 256>>>();

    const int mblk = (N_NODES + 127) / 128;   // 157
    const int nb = D_H / 64;                  // 4 col-blocks per matrix

    // fused: h1 = x@W1 ; hres = x@Wres + bres   (grid.y = 8: 0-3 -> W1, 4-7 -> Wres)
    tf32_gemm_kernel<D_IN><<<dim3(mblk, 2 * nb), 256>>>(
        x, N_NODES, nb, W1, nullptr, p_h1, Wres, bres, p_hres);

    scatter_kernel<<<2048, 256>>>(src, dst, ew, p_h1, E);
    ln1_kernel<<<N_NODES, D_H>>>(b1, gamma1, beta1);

    // h2 = h @ W2 (single matrix: grid.y = 4)
    tf32_gemm_kernel<D_H><<<dim3(mblk, nb), 256>>>(
        p_h, N_NODES, nb, W2, nullptr, p_h1, W2, nullptr, p_h1);

    scatter_kernel<<<2048, 256>>>(src, dst, ew, p_h1, E);
    ln2_kernel<<<N_NODES, D_H>>>(b2, gamma2, beta2, out);
}

// round 6
// speedup vs baseline: 1.6650x; 1.2417x over previous
#include <cuda_runtime.h>
#include <cuda_bf16.h>
#include <stdint.h>

#define N_NODES 20000
#define D_IN    128
#define D_H     256
#define LN_EPS  1e-5f
#define MAX_E   330000

// ---------------- scratch (no dynamic allocation allowed) ----------------
__device__ float g_deg [N_NODES];
__device__ int   g_cnt [N_NODES];
__device__ float g_dinv[N_NODES];
__device__ int   g_off [N_NODES + 1];
__device__ int   g_csr_src[MAX_E];
__device__ float g_csr_nrm[MAX_E];
__device__ float g_h1  [N_NODES * D_H];  // x@W1, later h@W2
__device__ float g_hres[N_NODES * D_H];  // x@Wres + bres
__device__ float g_h   [N_NODES * D_H];  // after LN1

// ---------------- helpers ----------------
__device__ __forceinline__ uint32_t f2tf32(float f) {
    uint32_t u;
    asm("cvt.rna.tf32.f32 %0, %1;" : "=r"(u) : "f"(f));
    return u;
}

__device__ __forceinline__ void mma_tf32(float* c, const uint32_t* a, const uint32_t* b) {
    asm volatile(
        "mma.sync.aligned.m16n8k8.row.col.f32.tf32.tf32.f32 "
        "{%0,%1,%2,%3}, {%4,%5,%6,%7}, {%8,%9}, {%0,%1,%2,%3};"
        : "+f"(c[0]), "+f"(c[1]), "+f"(c[2]), "+f"(c[3])
        : "r"(a[0]), "r"(a[1]), "r"(a[2]), "r"(a[3]), "r"(b[0]), "r"(b[1]));
}

// ---------------- init: deg = 1 (self loop), cnt = 0 ----------------
__global__ void init_kernel() {
    for (int i = blockIdx.x * blockDim.x + threadIdx.x; i < N_NODES;
         i += gridDim.x * blockDim.x) {
        g_deg[i] = 1.0f;
        g_cnt[i] = 0;
    }
}

// ---------------- degree + count accumulation over edges ----------------
__global__ void degcnt_kernel(const int* __restrict__ dst,
                              const float* __restrict__ w, int E) {
    for (int e = blockIdx.x * blockDim.x + threadIdx.x; e < E;
         e += gridDim.x * blockDim.x) {
        int d = dst[e];
        atomicAdd(&g_deg[d], w[e]);
        atomicAdd(&g_cnt[d], 1);
    }
}

__global__ void dinv_kernel() {
    for (int i = blockIdx.x * blockDim.x + threadIdx.x; i < N_NODES;
         i += gridDim.x * blockDim.x) {
        float d = g_deg[i];
        g_dinv[i] = d > 0.0f ? rsqrtf(d) : 0.0f;
    }
}

// ---------------- single-block exclusive scan of g_cnt -> g_off ------------
__global__ void scan_kernel() {
    __shared__ int part[1024];
    const int tid = threadIdx.x;
    const int CH = (N_NODES + 1023) / 1024;   // 20
    const int base = tid * CH;
    int s = 0;
    for (int i = 0; i < CH; i++) {
        int j = base + i;
        if (j < N_NODES) s += g_cnt[j];
    }
    part[tid] = s;
    __syncthreads();
    // inclusive Hillis-Steele scan
    for (int o = 1; o < 1024; o <<= 1) {
        int v = (tid >= o) ? part[tid - o] : 0;
        __syncthreads();
        part[tid] += v;
        __syncthreads();
    }
    int run = (tid == 0) ? 0 : part[tid - 1];
    for (int i = 0; i < CH; i++) {
        int j = base + i;
        if (j < N_NODES) {
            g_off[j] = run;
            run += g_cnt[j];
            g_cnt[j] = 0;          // reused as fill cursor
        }
    }
    if (tid == 1023) g_off[N_NODES] = run;
}

// ---------------- CSR fill (also precomputes edge norm) ----------------
__global__ void fill_kernel(const int* __restrict__ src,
                            const int* __restrict__ dst,
                            const float* __restrict__ w, int E) {
    for (int e = blockIdx.x * blockDim.x + threadIdx.x; e < E;
         e += gridDim.x * blockDim.x) {
        int s = src[e];
        int d = dst[e];
        int pos = g_off[d] + atomicAdd(&g_cnt[d], 1);
        g_csr_src[pos] = s;
        g_csr_nrm[pos] = g_dinv[s] * w[e] * g_dinv[d];
    }
}

// ---------------- TF32 tensor-core GEMM ----------------
// C[M,256] = A[M,K] @ B[K,256] (+bias), BM=128 BN=64 BK=16, 256 thr (8 warps).
// tf32 conversion done once at smem-store time.
template<int K>
__global__ __launch_bounds__(256)
void tf32_gemm_kernel(const float* __restrict__ A, int M, int nb,
                      const float* __restrict__ Bm1, const float* __restrict__ bias1,
                      float* __restrict__ C1,
                      const float* __restrict__ Bm2, const float* __restrict__ bias2,
                      float* __restrict__ C2) {
    __shared__ uint32_t As[128][20];   // [m][k] tf32 bits, stride 20
    __shared__ uint32_t Bs[16][72];    // [k][n] tf32 bits, stride 72

    const int tid  = threadIdx.x;
    const int lane = tid & 31;
    const int wid  = tid >> 5;
    const int wm   = (wid & 3) * 32;
    const int wn   = (wid >> 2) * 32;
    const int g    = lane >> 2;
    const int tg   = lane & 3;

    const int bm  = blockIdx.x * 128;
    const int mat = blockIdx.y / nb;
    const int bn  = (blockIdx.y % nb) * 64;

    const float* Bw   = mat ? Bm2   : Bm1;
    const float* bias = mat ? bias2 : bias1;
    float*       C    = mat ? C2    : C1;

    const int a_row = tid >> 1;
    const int a_k   = (tid & 1) * 4;
    const int b_kr  = tid >> 4;
    const int b_c   = (tid & 15) * 4;
    const bool a_ok = (bm + a_row) < M;
    const long a_base = (long)(bm + a_row) * K;

    float acc[2][4][4];
#pragma unroll
    for (int mt = 0; mt < 2; mt++)
#pragma unroll
        for (int nt = 0; nt < 4; nt++)
#pragma unroll
            for (int i = 0; i < 4; i++) acc[mt][nt][i] = 0.0f;

    float4 av0 = make_float4(0.f,0.f,0.f,0.f), av1 = av0;
    if (a_ok) {
        av0 = *reinterpret_cast<const float4*>(A + a_base + a_k);
        av1 = *reinterpret_cast<const float4*>(A + a_base + a_k + 8);
    }
    float4 bv = *reinterpret_cast<const float4*>(Bw + (long)b_kr * D_H + bn + b_c);

    const int T = K / 16;
    for (int t = 0; t < T; t++) {
        __syncthreads();
        As[a_row][a_k + 0] = f2tf32(av0.x); As[a_row][a_k + 1] = f2tf32(av0.y);
        As[a_row][a_k + 2] = f2tf32(av0.z); As[a_row][a_k + 3] = f2tf32(av0.w);
        As[a_row][a_k + 8] = f2tf32(av1.x); As[a_row][a_k + 9] = f2tf32(av1.y);
        As[a_row][a_k +10] = f2tf32(av1.z); As[a_row][a_k +11] = f2tf32(av1.w);
        Bs[b_kr][b_c + 0] = f2tf32(bv.x); Bs[b_kr][b_c + 1] = f2tf32(bv.y);
        Bs[b_kr][b_c + 2] = f2tf32(bv.z); Bs[b_kr][b_c + 3] = f2tf32(bv.w);
        __syncthreads();

        if (t + 1 < T) {
            int kt = (t + 1) * 16;
            av0 = make_float4(0.f,0.f,0.f,0.f); av1 = av0;
            if (a_ok) {
                av0 = *reinterpret_cast<const float4*>(A + a_base + kt + a_k);
                av1 = *reinterpret_cast<const float4*>(A + a_base + kt + a_k + 8);
            }
            bv = *reinterpret_cast<const float4*>(Bw + (long)(kt + b_kr) * D_H + bn + b_c);
        }

#pragma unroll
        for (int ks = 0; ks < 16; ks += 8) {
            uint32_t af[2][4], bf[4][2];
#pragma unroll
            for (int mt = 0; mt < 2; mt++) {
                int r0 = wm + mt * 16 + g;
                af[mt][0] = As[r0    ][ks + tg    ];
                af[mt][1] = As[r0 + 8][ks + tg    ];
                af[mt][2] = As[r0    ][ks + tg + 4];
                af[mt][3] = As[r0 + 8][ks + tg + 4];
            }
#pragma unroll
            for (int nt = 0; nt < 4; nt++) {
                int c0 = wn + nt * 8 + g;
                bf[nt][0] = Bs[ks + tg    ][c0];
                bf[nt][1] = Bs[ks + tg + 4][c0];
            }
#pragma unroll
            for (int mt = 0; mt < 2; mt++)
#pragma unroll
                for (int nt = 0; nt < 4; nt++)
                    mma_tf32(acc[mt][nt], af[mt], bf[nt]);
        }
    }

#pragma unroll
    for (int mt = 0; mt < 2; mt++) {
        int row = bm + wm + mt * 16 + g;
#pragma unroll
        for (int nt = 0; nt < 4; nt++) {
            int col = bn + wn + nt * 8 + tg * 2;
            float b0 = bias ? bias[col]     : 0.0f;
            float b1 = bias ? bias[col + 1] : 0.0f;
            if (row < M) {
                float2 o = make_float2(acc[mt][nt][0] + b0, acc[mt][nt][1] + b1);
                *reinterpret_cast<float2*>(C + (long)row * D_H + col) = o;
            }
            if (row + 8 < M) {
                float2 o = make_float2(acc[mt][nt][2] + b0, acc[mt][nt][3] + b1);
                *reinterpret_cast<float2*>(C + (long)(row + 8) * D_H + col) = o;
            }
        }
    }
}

// ---------------- block-wide mean/var helper ----------------
__device__ __forceinline__ void block_stats(float t, float& mu, float& var) {
    float s = t, sq = t * t;
#pragma unroll
    for (int o = 16; o; o >>= 1) {
        s  += __shfl_xor_sync(0xFFFFFFFFu, s, o);
        sq += __shfl_xor_sync(0xFFFFFFFFu, sq, o);
    }
    __shared__ float ss[8], ssq[8];
    int wid = threadIdx.x >> 5;
    if ((threadIdx.x & 31) == 0) { ss[wid] = s; ssq[wid] = sq; }
    __syncthreads();
    float ts = 0.f, tq = 0.f;
#pragma unroll
    for (int i = 0; i < 8; i++) { ts += ss[i]; tq += ssq[i]; }
    mu = ts * (1.0f / D_H);
    var = tq * (1.0f / D_H) - mu * mu;
}

// ---------------- fused CSR gather + (opt ReLU) + residual + LayerNorm ------
// one 256-thread block per dst row; edge meta staged in smem; MLP-4 gather.
template<bool RELU>
__global__ __launch_bounds__(256)
void gather_ln_kernel(const float* __restrict__ feat,
                      const float* __restrict__ resid,
                      const float* __restrict__ bias,
                      const float* __restrict__ gamma,
                      const float* __restrict__ beta,
                      float* __restrict__ out) {
    const int row = blockIdx.x;
    const int c = threadIdx.x;
    const long idx = (long)row * D_H + c;

    __shared__ int   s_src[64];
    __shared__ float s_nrm[64];

    const int beg = g_off[row];
    const int end = g_off[row + 1];
    const float di = g_dinv[row];

    // self-loop term: nrm_self = dinv^2 * 1
    float a0 = di * di * feat[idx];
    float a1 = 0.f, a2 = 0.f, a3 = 0.f;

    for (int chunk = beg; chunk < end; chunk += 64) {
        int n = min(64, end - chunk);
        __syncthreads();
        if (c < n) {
            s_src[c] = g_csr_src[chunk + c];
            s_nrm[c] = g_csr_nrm[chunk + c];
        }
        __syncthreads();
        int k = 0;
        for (; k + 4 <= n; k += 4) {
            a0 += s_nrm[k    ] * feat[(long)s_src[k    ] * D_H + c];
            a1 += s_nrm[k + 1] * feat[(long)s_src[k + 1] * D_H + c];
            a2 += s_nrm[k + 2] * feat[(long)s_src[k + 2] * D_H + c];
            a3 += s_nrm[k + 3] * feat[(long)s_src[k + 3] * D_H + c];
        }
        for (; k < n; k++)
            a0 += s_nrm[k] * feat[(long)s_src[k] * D_H + c];
    }

    float acc = (a0 + a1) + (a2 + a3) + bias[c];
    float t = RELU ? resid[idx] + fmaxf(acc, 0.0f) : resid[idx] + acc;

    float mu, var;
    block_stats(t, mu, var);
    out[idx] = (t - mu) * rsqrtf(var + LN_EPS) * gamma[c] + beta[c];
}

// ---------------- launch ----------------
extern "C" void kernel_launch(void* const* d_in, const int* in_sizes, int n_in,
                              void* d_out, int out_size) {
    const float* x      = (const float*)d_in[0];   // [20000,128]
    const int*   ei     = (const int*)d_in[1];     // [2,E] int32
    const float* ew     = (const float*)d_in[2];   // [E]
    const float* W1     = (const float*)d_in[3];
    const float* b1     = (const float*)d_in[4];
    const float* W2     = (const float*)d_in[5];
    const float* b2     = (const float*)d_in[6];
    const float* Wres   = (const float*)d_in[7];
    const float* bres   = (const float*)d_in[8];
    const float* gamma1 = (const float*)d_in[9];
    const float* beta1  = (const float*)d_in[10];
    const float* gamma2 = (const float*)d_in[11];
    const float* beta2  = (const float*)d_in[12];
    float* out = (float*)d_out;

    const int E = in_sizes[2];
    const int* src = ei;
    const int* dst = ei + E;

    // TRUE device addresses of scratch symbols (host name = host shadow).
    float *p_h1 = nullptr, *p_hres = nullptr, *p_h = nullptr;
    cudaGetSymbolAddress((void**)&p_h1,   g_h1);
    cudaGetSymbolAddress((void**)&p_hres, g_hres);
    cudaGetSymbolAddress((void**)&p_h,    g_h);

    // CSR build pipeline
    init_kernel<<<80, 256>>>();
    degcnt_kernel<<<(E + 255) / 256, 256>>>(dst, ew, E);
    dinv_kernel<<<(N_NODES + 255) / 256, 256>>>();
    scan_kernel<<<1, 1024>>>();
    fill_kernel<<<(E + 255) / 256, 256>>>(src, dst, ew, E);

    const int mblk = (N_NODES + 127) / 128;   // 157
    const int nb = D_H / 64;                  // 4 col-blocks per matrix

    // fused: h1 = x@W1 ; hres = x@Wres + bres
    tf32_gemm_kernel<D_IN><<<dim3(mblk, 2 * nb), 256>>>(
        x, N_NODES, nb, W1, nullptr, p_h1, Wres, bres, p_hres);

    // hop 0: gather(h1) + b1 + relu + hres residual + LN -> h
    gather_ln_kernel<true><<<N_NODES, D_H>>>(p_h1, p_hres, b1, gamma1, beta1, p_h);

    // h2 = h @ W2 (reuse g_h1)
    tf32_gemm_kernel<D_H><<<dim3(mblk, nb), 256>>>(
        p_h, N_NODES, nb, W2, nullptr, p_h1, W2, nullptr, p_h1);

    // hop 1: gather(h2) + b2 + h residual + LN -> out
    gather_ln_kernel<false><<<N_NODES, D_H>>>(p_h1, p_h, b2, gamma2, beta2, out);
}

// round 7
// speedup vs baseline: 1.8706x; 1.1235x over previous
#include <cuda_runtime.h>
#include <cuda_bf16.h>
#include <stdint.h>

#define N_NODES 20000
#define D_IN    128
#define D_H     256
#define LN_EPS  1e-5f
#define MAX_E   330000
#define NB_SCAN ((N_NODES + 255) / 256)   // 79

// ---------------- scratch (no dynamic allocation allowed) ----------------
__device__ float g_deg [N_NODES];
__device__ int   g_cnt [N_NODES];
__device__ float g_dinv[N_NODES];
__device__ int   g_off [N_NODES + 1];
__device__ int   g_blksum[NB_SCAN];
__device__ int   g_csr_src[MAX_E];
__device__ float g_csr_nrm[MAX_E];
__device__ float g_h1  [N_NODES * D_H];  // x@W1, later h@W2
__device__ float g_hres[N_NODES * D_H];  // x@Wres + bres
__device__ float g_h   [N_NODES * D_H];  // after LN1

// ---------------- helpers ----------------
__device__ __forceinline__ uint32_t f2tf32(float f) {
    uint32_t u;
    asm("cvt.rna.tf32.f32 %0, %1;" : "=r"(u) : "f"(f));
    return u;
}

__device__ __forceinline__ void mma_tf32(float* c, const uint32_t* a, const uint32_t* b) {
    asm volatile(
        "mma.sync.aligned.m16n8k8.row.col.f32.tf32.tf32.f32 "
        "{%0,%1,%2,%3}, {%4,%5,%6,%7}, {%8,%9}, {%0,%1,%2,%3};"
        : "+f"(c[0]), "+f"(c[1]), "+f"(c[2]), "+f"(c[3])
        : "r"(a[0]), "r"(a[1]), "r"(a[2]), "r"(a[3]), "r"(b[0]), "r"(b[1]));
}

// ---------------- init: deg = 1 (self loop), cnt = 0 ----------------
__global__ void init_kernel() {
    for (int i = blockIdx.x * blockDim.x + threadIdx.x; i < N_NODES;
         i += gridDim.x * blockDim.x) {
        g_deg[i] = 1.0f;
        g_cnt[i] = 0;
    }
}

// ---------------- degree + count accumulation over edges ----------------
__global__ void degcnt_kernel(const int* __restrict__ dst,
                              const float* __restrict__ w, int E) {
    for (int e = blockIdx.x * blockDim.x + threadIdx.x; e < E;
         e += gridDim.x * blockDim.x) {
        int d = dst[e];
        atomicAdd(&g_deg[d], w[e]);
        atomicAdd(&g_cnt[d], 1);
    }
}

// ---------------- scan pass 1: per-block exclusive scan + dinv --------------
__global__ void scan1_kernel() {
    const int t = threadIdx.x, b = blockIdx.x;
    const int i = b * 256 + t;
    const int lane = t & 31, wid = t >> 5;

    int v = (i < N_NODES) ? g_cnt[i] : 0;
    // fuse dinv computation (needs g_deg only)
    if (i < N_NODES) {
        float d = g_deg[i];
        g_dinv[i] = d > 0.0f ? rsqrtf(d) : 0.0f;
    }

    int s = v;
#pragma unroll
    for (int o = 1; o < 32; o <<= 1) {
        int u = __shfl_up_sync(0xFFFFFFFFu, s, o);
        if (lane >= o) s += u;
    }
    __shared__ int wsum[8];
    if (lane == 31) wsum[wid] = s;
    __syncthreads();
    int base = 0;
#pragma unroll
    for (int w = 0; w < 8; w++) base += (w < wid) ? wsum[w] : 0;
    if (i < N_NODES) g_off[i] = base + s - v;      // within-block exclusive
    if (t == 255) g_blksum[b] = base + s;          // block total
}

// ---------------- scan pass 2: add block bases, reset cursors ---------------
__global__ void scan2_kernel(int E) {
    const int t = threadIdx.x, b = blockIdx.x;
    __shared__ int sbase;
    if (t < 32) {
        int acc = 0;
        for (int j = t; j < b; j += 32) acc += g_blksum[j];
#pragma unroll
        for (int o = 16; o; o >>= 1) acc += __shfl_xor_sync(0xFFFFFFFFu, acc, o);
        if (t == 0) sbase = acc;
    }
    __syncthreads();
    const int i = b * 256 + t;
    if (i < N_NODES) {
        g_off[i] += sbase;
        g_cnt[i] = 0;          // reused as fill cursor
    }
    if (b == 0 && t == 0) g_off[N_NODES] = E;
}

// ---------------- CSR fill (also precomputes edge norm) ----------------
__global__ void fill_kernel(const int* __restrict__ src,
                            const int* __restrict__ dst,
                            const float* __restrict__ w, int E) {
    for (int e = blockIdx.x * blockDim.x + threadIdx.x; e < E;
         e += gridDim.x * blockDim.x) {
        int s = src[e];
        int d = dst[e];
        int pos = g_off[d] + atomicAdd(&g_cnt[d], 1);
        g_csr_src[pos] = s;
        g_csr_nrm[pos] = g_dinv[s] * w[e] * g_dinv[d];
    }
}

// ---------------- TF32 tensor-core GEMM ----------------
// C[M,256] = A[M,K] @ B[K,256] (+bias). BM=128 BN=128 BK=16, 256 thr (8 warps).
// Warp tile 64x32 (mt=4, nt=4) -> 1.5 LDS/mma. tf32 cvt at smem-store time.
// Dual mode: grid.y in [0, 2*nb): by/nb selects (B1,bias1,C1) vs (B2,bias2,C2).
template<int K>
__global__ __launch_bounds__(256)
void tf32_gemm_kernel(const float* __restrict__ A, int M, int nb,
                      const float* __restrict__ Bm1, const float* __restrict__ bias1,
                      float* __restrict__ C1,
                      const float* __restrict__ Bm2, const float* __restrict__ bias2,
                      float* __restrict__ C2) {
    __shared__ uint32_t As[128][20];    // stride 20 -> conflict-free frag loads
    __shared__ uint32_t Bs[16][136];    // stride 136 (≡8 mod 32) -> conflict-free

    const int tid  = threadIdx.x;
    const int lane = tid & 31;
    const int wid  = tid >> 5;
    const int wm   = (wid & 1) * 64;    // warp m offset (2 warps in m)
    const int wn   = (wid >> 1) * 32;   // warp n offset (4 warps in n)
    const int g    = lane >> 2;
    const int tg   = lane & 3;

    const int bm  = blockIdx.x * 128;
    const int mat = blockIdx.y / nb;
    const int bn  = (blockIdx.y % nb) * 128;

    const float* Bw   = mat ? Bm2   : Bm1;
    const float* bias = mat ? bias2 : bias1;
    float*       C    = mat ? C2    : C1;

    // loader mapping
    const int a_row = tid >> 1;          // 0..127
    const int a_k   = (tid & 1) * 4;     // 0/4; second float4 at +8
    const int b_kr  = tid >> 5;          // 0..7; second row at +8
    const int b_c   = lane * 4;          // 0..124
    const bool a_ok = (bm + a_row) < M;
    const long a_base = (long)(bm + a_row) * K;

    float acc[4][4][4];
#pragma unroll
    for (int mt = 0; mt < 4; mt++)
#pragma unroll
        for (int nt = 0; nt < 4; nt++)
#pragma unroll
            for (int i = 0; i < 4; i++) acc[mt][nt][i] = 0.0f;

    // preload tile 0
    float4 av0 = make_float4(0.f,0.f,0.f,0.f), av1 = av0;
    if (a_ok) {
        av0 = *reinterpret_cast<const float4*>(A + a_base + a_k);
        av1 = *reinterpret_cast<const float4*>(A + a_base + a_k + 8);
    }
    float4 bv0 = *reinterpret_cast<const float4*>(Bw + (long)b_kr * D_H + bn + b_c);
    float4 bv1 = *reinterpret_cast<const float4*>(Bw + (long)(b_kr + 8) * D_H + bn + b_c);

    const int T = K / 16;
    for (int t = 0; t < T; t++) {
        __syncthreads();
        {
            uint4 pa0 = make_uint4(f2tf32(av0.x), f2tf32(av0.y), f2tf32(av0.z), f2tf32(av0.w));
            uint4 pa1 = make_uint4(f2tf32(av1.x), f2tf32(av1.y), f2tf32(av1.z), f2tf32(av1.w));
            *reinterpret_cast<uint4*>(&As[a_row][a_k])     = pa0;
            *reinterpret_cast<uint4*>(&As[a_row][a_k + 8]) = pa1;
            uint4 pb0 = make_uint4(f2tf32(bv0.x), f2tf32(bv0.y), f2tf32(bv0.z), f2tf32(bv0.w));
            uint4 pb1 = make_uint4(f2tf32(bv1.x), f2tf32(bv1.y), f2tf32(bv1.z), f2tf32(bv1.w));
            *reinterpret_cast<uint4*>(&Bs[b_kr][b_c])     = pb0;
            *reinterpret_cast<uint4*>(&Bs[b_kr + 8][b_c]) = pb1;
        }
        __syncthreads();

        if (t + 1 < T) {   // prefetch next tile (overlaps mma block)
            int kt = (t + 1) * 16;
            av0 = make_float4(0.f,0.f,0.f,0.f); av1 = av0;
            if (a_ok) {
                av0 = *reinterpret_cast<const float4*>(A + a_base + kt + a_k);
                av1 = *reinterpret_cast<const float4*>(A + a_base + kt + a_k + 8);
            }
            bv0 = *reinterpret_cast<const float4*>(Bw + (long)(kt + b_kr) * D_H + bn + b_c);
            bv1 = *reinterpret_cast<const float4*>(Bw + (long)(kt + b_kr + 8) * D_H + bn + b_c);
        }

#pragma unroll
        for (int ks = 0; ks < 16; ks += 8) {
            uint32_t af[4][4], bf[4][2];
#pragma unroll
            for (int mt = 0; mt < 4; mt++) {
                int r0 = wm + mt * 16 + g;
                af[mt][0] = As[r0    ][ks + tg    ];
                af[mt][1] = As[r0 + 8][ks + tg    ];
                af[mt][2] = As[r0    ][ks + tg + 4];
                af[mt][3] = As[r0 + 8][ks + tg + 4];
            }
#pragma unroll
            for (int nt = 0; nt < 4; nt++) {
                int c0 = wn + nt * 8 + g;
                bf[nt][0] = Bs[ks + tg    ][c0];
                bf[nt][1] = Bs[ks + tg + 4][c0];
            }
#pragma unroll
            for (int mt = 0; mt < 4; mt++)
#pragma unroll
                for (int nt = 0; nt < 4; nt++)
                    mma_tf32(acc[mt][nt], af[mt], bf[nt]);
        }
    }

#pragma unroll
    for (int mt = 0; mt < 4; mt++) {
        int row = bm + wm + mt * 16 + g;
#pragma unroll
        for (int nt = 0; nt < 4; nt++) {
            int col = bn + wn + nt * 8 + tg * 2;
            float b0 = bias ? bias[col]     : 0.0f;
            float b1 = bias ? bias[col + 1] : 0.0f;
            if (row < M) {
                float2 o = make_float2(acc[mt][nt][0] + b0, acc[mt][nt][1] + b1);
                *reinterpret_cast<float2*>(C + (long)row * D_H + col) = o;
            }
            if (row + 8 < M) {
                float2 o = make_float2(acc[mt][nt][2] + b0, acc[mt][nt][3] + b1);
                *reinterpret_cast<float2*>(C + (long)(row + 8) * D_H + col) = o;
            }
        }
    }
}

// ---------------- block-wide mean/var helper ----------------
__device__ __forceinline__ void block_stats(float t, float& mu, float& var) {
    float s = t, sq = t * t;
#pragma unroll
    for (int o = 16; o; o >>= 1) {
        s  += __shfl_xor_sync(0xFFFFFFFFu, s, o);
        sq += __shfl_xor_sync(0xFFFFFFFFu, sq, o);
    }
    __shared__ float ss[8], ssq[8];
    int wid = threadIdx.x >> 5;
    if ((threadIdx.x & 31) == 0) { ss[wid] = s; ssq[wid] = sq; }
    __syncthreads();
    float ts = 0.f, tq = 0.f;
#pragma unroll
    for (int i = 0; i < 8; i++) { ts += ss[i]; tq += ssq[i]; }
    mu = ts * (1.0f / D_H);
    var = tq * (1.0f / D_H) - mu * mu;
}

// ---------------- fused CSR gather + (opt ReLU) + residual + LayerNorm ------
template<bool RELU>
__global__ __launch_bounds__(256)
void gather_ln_kernel(const float* __restrict__ feat,
                      const float* __restrict__ resid,
                      const float* __restrict__ bias,
                      const float* __restrict__ gamma,
                      const float* __restrict__ beta,
                      float* __restrict__ out) {
    const int row = blockIdx.x;
    const int c = threadIdx.x;
    const long idx = (long)row * D_H + c;

    __shared__ int   s_src[64];
    __shared__ float s_nrm[64];

    const int beg = g_off[row];
    const int end = g_off[row + 1];
    const float di = g_dinv[row];

    // self-loop term: nrm_self = dinv^2 * 1
    float a0 = di * di * feat[idx];
    float a1 = 0.f, a2 = 0.f, a3 = 0.f;

    for (int chunk = beg; chunk < end; chunk += 64) {
        int n = min(64, end - chunk);
        if (chunk != beg) __syncthreads();   // protect overwrite only
        if (c < n) {
            s_src[c] = g_csr_src[chunk + c];
            s_nrm[c] = g_csr_nrm[chunk + c];
        }
        __syncthreads();
        int k = 0;
        for (; k + 4 <= n; k += 4) {
            a0 += s_nrm[k    ] * feat[(long)s_src[k    ] * D_H + c];
            a1 += s_nrm[k + 1] * feat[(long)s_src[k + 1] * D_H + c];
            a2 += s_nrm[k + 2] * feat[(long)s_src[k + 2] * D_H + c];
            a3 += s_nrm[k + 3] * feat[(long)s_src[k + 3] * D_H + c];
        }
        for (; k < n; k++)
            a0 += s_nrm[k] * feat[(long)s_src[k] * D_H + c];
    }

    float acc = (a0 + a1) + (a2 + a3) + bias[c];
    float t = RELU ? resid[idx] + fmaxf(acc, 0.0f) : resid[idx] + acc;

    float mu, var;
    block_stats(t, mu, var);
    out[idx] = (t - mu) * rsqrtf(var + LN_EPS) * gamma[c] + beta[c];
}

// ---------------- launch ----------------
extern "C" void kernel_launch(void* const* d_in, const int* in_sizes, int n_in,
                              void* d_out, int out_size) {
    const float* x      = (const float*)d_in[0];   // [20000,128]
    const int*   ei     = (const int*)d_in[1];     // [2,E] int32
    const float* ew     = (const float*)d_in[2];   // [E]
    const float* W1     = (const float*)d_in[3];
    const float* b1     = (const float*)d_in[4];
    const float* W2     = (const float*)d_in[5];
    const float* b2     = (const float*)d_in[6];
    const float* Wres   = (const float*)d_in[7];
    const float* bres   = (const float*)d_in[8];
    const float* gamma1 = (const float*)d_in[9];
    const float* beta1  = (const float*)d_in[10];
    const float* gamma2 = (const float*)d_in[11];
    const float* beta2  = (const float*)d_in[12];
    float* out = (float*)d_out;

    const int E = in_sizes[2];
    const int* src = ei;
    const int* dst = ei + E;

    // TRUE device addresses of scratch symbols (host name = host shadow).
    float *p_h1 = nullptr, *p_hres = nullptr, *p_h = nullptr;
    cudaGetSymbolAddress((void**)&p_h1,   g_h1);
    cudaGetSymbolAddress((void**)&p_hres, g_hres);
    cudaGetSymbolAddress((void**)&p_h,    g_h);

    // CSR build pipeline
    init_kernel<<<80, 256>>>();
    degcnt_kernel<<<(E + 255) / 256, 256>>>(dst, ew, E);
    scan1_kernel<<<NB_SCAN, 256>>>();
    scan2_kernel<<<NB_SCAN, 256>>>(E);
    fill_kernel<<<(E + 255) / 256, 256>>>(src, dst, ew, E);

    const int mblk = (N_NODES + 127) / 128;   // 157
    const int nb = D_H / 128;                 // 2 col-blocks per matrix

    // fused: h1 = x@W1 ; hres = x@Wres + bres
    tf32_gemm_kernel<D_IN><<<dim3(mblk, 2 * nb), 256>>>(
        x, N_NODES, nb, W1, nullptr, p_h1, Wres, bres, p_hres);

    // hop 0: gather(h1) + b1 + relu + hres residual + LN -> h
    gather_ln_kernel<true><<<N_NODES, D_H>>>(p_h1, p_hres, b1, gamma1, beta1, p_h);

    // h2 = h @ W2 (reuse g_h1)
    tf32_gemm_kernel<D_H><<<dim3(mblk, nb), 256>>>(
        p_h, N_NODES, nb, W2, nullptr, p_h1, W2, nullptr, p_h1);

    // hop 1: gather(h2) + b2 + h residual + LN -> out
    gather_ln_kernel<false><<<N_NODES, D_H>>>(p_h1, p_h, b2, gamma2, beta2, out);
}

// round 8
// speedup vs baseline: 1.9668x; 1.0514x over previous
#include <cuda_runtime.h>
#include <cuda_bf16.h>
#include <stdint.h>

#define N_NODES 20000
#define D_IN    128
#define D_H     256
#define LN_EPS  1e-5f
#define MAX_E   330000
#define NB_SCAN ((N_NODES + 255) / 256)   // 79

// ---------------- scratch (no dynamic allocation allowed) ----------------
__device__ float g_deg [N_NODES];
__device__ int   g_cnt [N_NODES];
__device__ float g_dinv[N_NODES];
__device__ int   g_off [N_NODES + 1];
__device__ int   g_blksum[NB_SCAN];
__device__ int   g_csr_src[MAX_E];
__device__ float g_csr_nrm[MAX_E];
__device__ float g_h1  [N_NODES * D_H];  // x@W1, later h@W2
__device__ float g_hres[N_NODES * D_H];  // x@Wres + bres
__device__ float g_h   [N_NODES * D_H];  // after LN1

// ---------------- helpers ----------------
__device__ __forceinline__ uint32_t f2tf32(float f) {
    uint32_t u;
    asm("cvt.rna.tf32.f32 %0, %1;" : "=r"(u) : "f"(f));
    return u;
}

__device__ __forceinline__ void mma_tf32(float* c, const uint32_t* a, const uint32_t* b) {
    asm volatile(
        "mma.sync.aligned.m16n8k8.row.col.f32.tf32.tf32.f32 "
        "{%0,%1,%2,%3}, {%4,%5,%6,%7}, {%8,%9}, {%0,%1,%2,%3};"
        : "+f"(c[0]), "+f"(c[1]), "+f"(c[2]), "+f"(c[3])
        : "r"(a[0]), "r"(a[1]), "r"(a[2]), "r"(a[3]), "r"(b[0]), "r"(b[1]));
}

// ---------------- init: deg = 1 (self loop), cnt = 0 ----------------
__global__ void init_kernel() {
    for (int i = blockIdx.x * blockDim.x + threadIdx.x; i < N_NODES;
         i += gridDim.x * blockDim.x) {
        g_deg[i] = 1.0f;
        g_cnt[i] = 0;
    }
}

// ---------------- degree + count accumulation over edges ----------------
__global__ void degcnt_kernel(const int* __restrict__ dst,
                              const float* __restrict__ w, int E) {
    for (int e = blockIdx.x * blockDim.x + threadIdx.x; e < E;
         e += gridDim.x * blockDim.x) {
        int d = dst[e];
        atomicAdd(&g_deg[d], w[e]);
        atomicAdd(&g_cnt[d], 1);
    }
}

// ---------------- scan pass 1: per-block exclusive scan + dinv --------------
__global__ void scan1_kernel() {
    const int t = threadIdx.x, b = blockIdx.x;
    const int i = b * 256 + t;
    const int lane = t & 31, wid = t >> 5;

    int v = (i < N_NODES) ? g_cnt[i] : 0;
    if (i < N_NODES) {
        float d = g_deg[i];
        g_dinv[i] = d > 0.0f ? rsqrtf(d) : 0.0f;
    }

    int s = v;
#pragma unroll
    for (int o = 1; o < 32; o <<= 1) {
        int u = __shfl_up_sync(0xFFFFFFFFu, s, o);
        if (lane >= o) s += u;
    }
    __shared__ int wsum[8];
    if (lane == 31) wsum[wid] = s;
    __syncthreads();
    int base = 0;
#pragma unroll
    for (int w = 0; w < 8; w++) base += (w < wid) ? wsum[w] : 0;
    if (i < N_NODES) g_off[i] = base + s - v;      // within-block exclusive
    if (t == 255) g_blksum[b] = base + s;          // block total
}

// ---------------- scan pass 2: add block bases, reset cursors ---------------
__global__ void scan2_kernel(int E) {
    const int t = threadIdx.x, b = blockIdx.x;
    __shared__ int sbase;
    if (t < 32) {
        int acc = 0;
        for (int j = t; j < b; j += 32) acc += g_blksum[j];
#pragma unroll
        for (int o = 16; o; o >>= 1) acc += __shfl_xor_sync(0xFFFFFFFFu, acc, o);
        if (t == 0) sbase = acc;
    }
    __syncthreads();
    const int i = b * 256 + t;
    if (i < N_NODES) {
        g_off[i] += sbase;
        g_cnt[i] = 0;          // reused as fill cursor
    }
    if (b == 0 && t == 0) g_off[N_NODES] = E;
}

// ---------------- CSR fill (also precomputes edge norm) ----------------
__global__ void fill_kernel(const int* __restrict__ src,
                            const int* __restrict__ dst,
                            const float* __restrict__ w, int E) {
    for (int e = blockIdx.x * blockDim.x + threadIdx.x; e < E;
         e += gridDim.x * blockDim.x) {
        int s = src[e];
        int d = dst[e];
        int pos = g_off[d] + atomicAdd(&g_cnt[d], 1);
        g_csr_src[pos] = s;
        g_csr_nrm[pos] = g_dinv[s] * w[e] * g_dinv[d];
    }
}

// ---------------- TF32 tensor-core GEMM ----------------
// C[M,256] = A[M,K] @ B[K,256] (+bias). BM=128 BN=128 BK=16, 256 thr (8 warps).
// Warp tile 64x32 (mt=4, nt=4). tf32 cvt at smem-store time.
template<int K>
__global__ __launch_bounds__(256)
void tf32_gemm_kernel(const float* __restrict__ A, int M, int nb,
                      const float* __restrict__ Bm1, const float* __restrict__ bias1,
                      float* __restrict__ C1,
                      const float* __restrict__ Bm2, const float* __restrict__ bias2,
                      float* __restrict__ C2) {
    __shared__ uint32_t As[128][20];    // stride 20 -> conflict-free frag loads
    __shared__ uint32_t Bs[16][136];    // stride 136 (≡8 mod 32) -> conflict-free

    const int tid  = threadIdx.x;
    const int lane = tid & 31;
    const int wid  = tid >> 5;
    const int wm   = (wid & 1) * 64;
    const int wn   = (wid >> 1) * 32;
    const int g    = lane >> 2;
    const int tg   = lane & 3;

    const int bm  = blockIdx.x * 128;
    const int mat = blockIdx.y / nb;
    const int bn  = (blockIdx.y % nb) * 128;

    const float* Bw   = mat ? Bm2   : Bm1;
    const float* bias = mat ? bias2 : bias1;
    float*       C    = mat ? C2    : C1;

    const int a_row = tid >> 1;
    const int a_k   = (tid & 1) * 4;
    const int b_kr  = tid >> 5;
    const int b_c   = lane * 4;
    const bool a_ok = (bm + a_row) < M;
    const long a_base = (long)(bm + a_row) * K;

    float acc[4][4][4];
#pragma unroll
    for (int mt = 0; mt < 4; mt++)
#pragma unroll
        for (int nt = 0; nt < 4; nt++)
#pragma unroll
            for (int i = 0; i < 4; i++) acc[mt][nt][i] = 0.0f;

    float4 av0 = make_float4(0.f,0.f,0.f,0.f), av1 = av0;
    if (a_ok) {
        av0 = *reinterpret_cast<const float4*>(A + a_base + a_k);
        av1 = *reinterpret_cast<const float4*>(A + a_base + a_k + 8);
    }
    float4 bv0 = *reinterpret_cast<const float4*>(Bw + (long)b_kr * D_H + bn + b_c);
    float4 bv1 = *reinterpret_cast<const float4*>(Bw + (long)(b_kr + 8) * D_H + bn + b_c);

    const int T = K / 16;
    for (int t = 0; t < T; t++) {
        __syncthreads();
        {
            uint4 pa0 = make_uint4(f2tf32(av0.x), f2tf32(av0.y), f2tf32(av0.z), f2tf32(av0.w));
            uint4 pa1 = make_uint4(f2tf32(av1.x), f2tf32(av1.y), f2tf32(av1.z), f2tf32(av1.w));
            *reinterpret_cast<uint4*>(&As[a_row][a_k])     = pa0;
            *reinterpret_cast<uint4*>(&As[a_row][a_k + 8]) = pa1;
            uint4 pb0 = make_uint4(f2tf32(bv0.x), f2tf32(bv0.y), f2tf32(bv0.z), f2tf32(bv0.w));
            uint4 pb1 = make_uint4(f2tf32(bv1.x), f2tf32(bv1.y), f2tf32(bv1.z), f2tf32(bv1.w));
            *reinterpret_cast<uint4*>(&Bs[b_kr][b_c])     = pb0;
            *reinterpret_cast<uint4*>(&Bs[b_kr + 8][b_c]) = pb1;
        }
        __syncthreads();

        if (t + 1 < T) {
            int kt = (t + 1) * 16;
            av0 = make_float4(0.f,0.f,0.f,0.f); av1 = av0;
            if (a_ok) {
                av0 = *reinterpret_cast<const float4*>(A + a_base + kt + a_k);
                av1 = *reinterpret_cast<const float4*>(A + a_base + kt + a_k + 8);
            }
            bv0 = *reinterpret_cast<const float4*>(Bw + (long)(kt + b_kr) * D_H + bn + b_c);
            bv1 = *reinterpret_cast<const float4*>(Bw + (long)(kt + b_kr + 8) * D_H + bn + b_c);
        }

#pragma unroll
        for (int ks = 0; ks < 16; ks += 8) {
            uint32_t af[4][4], bf[4][2];
#pragma unroll
            for (int mt = 0; mt < 4; mt++) {
                int r0 = wm + mt * 16 + g;
                af[mt][0] = As[r0    ][ks + tg    ];
                af[mt][1] = As[r0 + 8][ks + tg    ];
                af[mt][2] = As[r0    ][ks + tg + 4];
                af[mt][3] = As[r0 + 8][ks + tg + 4];
            }
#pragma unroll
            for (int nt = 0; nt < 4; nt++) {
                int c0 = wn + nt * 8 + g;
                bf[nt][0] = Bs[ks + tg    ][c0];
                bf[nt][1] = Bs[ks + tg + 4][c0];
            }
#pragma unroll
            for (int mt = 0; mt < 4; mt++)
#pragma unroll
                for (int nt = 0; nt < 4; nt++)
                    mma_tf32(acc[mt][nt], af[mt], bf[nt]);
        }
    }

#pragma unroll
    for (int mt = 0; mt < 4; mt++) {
        int row = bm + wm + mt * 16 + g;
#pragma unroll
        for (int nt = 0; nt < 4; nt++) {
            int col = bn + wn + nt * 8 + tg * 2;
            float b0 = bias ? bias[col]     : 0.0f;
            float b1 = bias ? bias[col + 1] : 0.0f;
            if (row < M) {
                float2 o = make_float2(acc[mt][nt][0] + b0, acc[mt][nt][1] + b1);
                *reinterpret_cast<float2*>(C + (long)row * D_H + col) = o;
            }
            if (row + 8 < M) {
                float2 o = make_float2(acc[mt][nt][2] + b0, acc[mt][nt][3] + b1);
                *reinterpret_cast<float2*>(C + (long)(row + 8) * D_H + col) = o;
            }
        }
    }
}

// ---------------- block-wide mean/var helper ----------------
__device__ __forceinline__ void block_stats(float t, float& mu, float& var) {
    float s = t, sq = t * t;
#pragma unroll
    for (int o = 16; o; o >>= 1) {
        s  += __shfl_xor_sync(0xFFFFFFFFu, s, o);
        sq += __shfl_xor_sync(0xFFFFFFFFu, sq, o);
    }
    __shared__ float ss[8], ssq[8];
    int wid = threadIdx.x >> 5;
    if ((threadIdx.x & 31) == 0) { ss[wid] = s; ssq[wid] = sq; }
    __syncthreads();
    float ts = 0.f, tq = 0.f;
#pragma unroll
    for (int i = 0; i < 8; i++) { ts += ss[i]; tq += ssq[i]; }
    mu = ts * (1.0f / D_H);
    var = tq * (1.0f / D_H) - mu * mu;
}

// ---------------- fused CSR gather + (opt ReLU) + residual + LayerNorm ------
template<bool RELU>
__global__ __launch_bounds__(256)
void gather_ln_kernel(const float* __restrict__ feat,
                      const float* __restrict__ resid,
                      const float* __restrict__ bias,
                      const float* __restrict__ gamma,
                      const float* __restrict__ beta,
                      float* __restrict__ out) {
    const int row = blockIdx.x;
    const int c = threadIdx.x;
    const long idx = (long)row * D_H + c;

    __shared__ int   s_src[64];
    __shared__ float s_nrm[64];

    const int beg = g_off[row];
    const int end = g_off[row + 1];
    const float di = g_dinv[row];

    float a0 = di * di * feat[idx];   // self-loop
    float a1 = 0.f, a2 = 0.f, a3 = 0.f;

    for (int chunk = beg; chunk < end; chunk += 64) {
        int n = min(64, end - chunk);
        if (chunk != beg) __syncthreads();
        if (c < n) {
            s_src[c] = g_csr_src[chunk + c];
            s_nrm[c] = g_csr_nrm[chunk + c];
        }
        __syncthreads();
        int k = 0;
        for (; k + 4 <= n; k += 4) {
            a0 += s_nrm[k    ] * feat[(long)s_src[k    ] * D_H + c];
            a1 += s_nrm[k + 1] * feat[(long)s_src[k + 1] * D_H + c];
            a2 += s_nrm[k + 2] * feat[(long)s_src[k + 2] * D_H + c];
            a3 += s_nrm[k + 3] * feat[(long)s_src[k + 3] * D_H + c];
        }
        for (; k < n; k++)
            a0 += s_nrm[k] * feat[(long)s_src[k] * D_H + c];
    }

    float acc = (a0 + a1) + (a2 + a3) + bias[c];
    float t = RELU ? resid[idx] + fmaxf(acc, 0.0f) : resid[idx] + acc;

    float mu, var;
    block_stats(t, mu, var);
    out[idx] = (t - mu) * rsqrtf(var + LN_EPS) * gamma[c] + beta[c];
}

// ---------------- launch ----------------
extern "C" void kernel_launch(void* const* d_in, const int* in_sizes, int n_in,
                              void* d_out, int out_size) {
    const float* x      = (const float*)d_in[0];
    const int*   ei     = (const int*)d_in[1];     // [2,E] int32
    const float* ew     = (const float*)d_in[2];
    const float* W1     = (const float*)d_in[3];
    const float* b1     = (const float*)d_in[4];
    const float* W2     = (const float*)d_in[5];
    const float* b2     = (const float*)d_in[6];
    const float* Wres   = (const float*)d_in[7];
    const float* bres   = (const float*)d_in[8];
    const float* gamma1 = (const float*)d_in[9];
    const float* beta1  = (const float*)d_in[10];
    const float* gamma2 = (const float*)d_in[11];
    const float* beta2  = (const float*)d_in[12];
    float* out = (float*)d_out;

    const int E = in_sizes[2];
    const int* src = ei;
    const int* dst = ei + E;

    float *p_h1 = nullptr, *p_hres = nullptr, *p_h = nullptr;
    cudaGetSymbolAddress((void**)&p_h1,   g_h1);
    cudaGetSymbolAddress((void**)&p_hres, g_hres);
    cudaGetSymbolAddress((void**)&p_h,    g_h);

    // lazily-created side stream + events (host resources only; identical
    // work on every call, so capture/determinism rules hold)
    static cudaStream_t sideStream = nullptr;
    static cudaEvent_t  evFork = nullptr, evJoin = nullptr;
    if (!sideStream) {
        if (cudaStreamCreateWithFlags(&sideStream, cudaStreamNonBlocking) != cudaSuccess)
            sideStream = nullptr;
        if (sideStream) {
            cudaEventCreateWithFlags(&evFork, cudaEventDisableTiming);
            cudaEventCreateWithFlags(&evJoin, cudaEventDisableTiming);
        }
    }
    cudaStream_t cs = sideStream ? sideStream : (cudaStream_t)0;

    // fork: CSR build chain on side stream
    if (sideStream) {
        cudaEventRecord(evFork, 0);
        cudaStreamWaitEvent(sideStream, evFork, 0);
    }
    init_kernel<<<80, 256, 0, cs>>>();
    degcnt_kernel<<<(E + 255) / 256, 256, 0, cs>>>(dst, ew, E);
    scan1_kernel<<<NB_SCAN, 256, 0, cs>>>();
    scan2_kernel<<<NB_SCAN, 256, 0, cs>>>(E);
    fill_kernel<<<(E + 255) / 256, 256, 0, cs>>>(src, dst, ew, E);
    if (sideStream) cudaEventRecord(evJoin, sideStream);

    const int mblk = (N_NODES + 127) / 128;   // 157
    const int nb = D_H / 128;                 // 2 col-blocks per matrix

    // main stream (concurrent with CSR build): h1 = x@W1 ; hres = x@Wres + bres
    tf32_gemm_kernel<D_IN><<<dim3(mblk, 2 * nb), 256>>>(
        x, N_NODES, nb, W1, nullptr, p_h1, Wres, bres, p_hres);

    // join: gather needs both CSR and GEMM results
    if (sideStream) cudaStreamWaitEvent((cudaStream_t)0, evJoin, 0);

    // hop 0: gather(h1) + b1 + relu + hres residual + LN -> h
    gather_ln_kernel<true><<<N_NODES, D_H>>>(p_h1, p_hres, b1, gamma1, beta1, p_h);

    // h2 = h @ W2 (reuse g_h1)
    tf32_gemm_kernel<D_H><<<dim3(mblk, nb), 256>>>(
        p_h, N_NODES, nb, W2, nullptr, p_h1, W2, nullptr, p_h1);

    // hop 1: gather(h2) + b2 + h residual + LN -> out
    gather_ln_kernel<false><<<N_NODES, D_H>>>(p_h1, p_h, b2, gamma2, beta2, out);
}

// round 9
// speedup vs baseline: 2.0466x; 1.0406x over previous
#include <cuda_runtime.h>
#include <cuda_fp16.h>
#include <stdint.h>

#define N_NODES 20000
#define D_IN    128
#define D_H     256
#define LN_EPS  1e-5f
#define MAX_E   330000
#define NB_SCAN ((N_NODES + 255) / 256)   // 79

// ---------------- scratch (no dynamic allocation allowed) ----------------
__device__ float  g_deg [N_NODES];
__device__ int    g_cnt [N_NODES];
__device__ float  g_dinv[N_NODES];
__device__ int    g_off [N_NODES + 1];
__device__ int    g_blksum[NB_SCAN];
__device__ int    g_csr_src[MAX_E];
__device__ float  g_csr_nrm[MAX_E];
__device__ __half g_h1h [N_NODES * D_H];  // x@W1 (fp16), later h@W2 (fp16)
__device__ float  g_hres[N_NODES * D_H];  // x@Wres + bres
__device__ float  g_h   [N_NODES * D_H];  // after LN1

// ---------------- helpers ----------------
__device__ __forceinline__ uint32_t f2tf32(float f) {
    uint32_t u;
    asm("cvt.rna.tf32.f32 %0, %1;" : "=r"(u) : "f"(f));
    return u;
}

__device__ __forceinline__ void mma_tf32(float* c, const uint32_t* a, const uint32_t* b) {
    asm volatile(
        "mma.sync.aligned.m16n8k8.row.col.f32.tf32.tf32.f32 "
        "{%0,%1,%2,%3}, {%4,%5,%6,%7}, {%8,%9}, {%0,%1,%2,%3};"
        : "+f"(c[0]), "+f"(c[1]), "+f"(c[2]), "+f"(c[3])
        : "r"(a[0]), "r"(a[1]), "r"(a[2]), "r"(a[3]), "r"(b[0]), "r"(b[1]));
}

// ---------------- init: deg = 1 (self loop), cnt = 0 ----------------
__global__ void init_kernel() {
    for (int i = blockIdx.x * blockDim.x + threadIdx.x; i < N_NODES;
         i += gridDim.x * blockDim.x) {
        g_deg[i] = 1.0f;
        g_cnt[i] = 0;
    }
}

// ---------------- degree + count accumulation over edges ----------------
__global__ void degcnt_kernel(const int* __restrict__ dst,
                              const float* __restrict__ w, int E) {
    for (int e = blockIdx.x * blockDim.x + threadIdx.x; e < E;
         e += gridDim.x * blockDim.x) {
        int d = dst[e];
        atomicAdd(&g_deg[d], w[e]);
        atomicAdd(&g_cnt[d], 1);
    }
}

// ---------------- scan pass 1: per-block exclusive scan + dinv --------------
__global__ void scan1_kernel() {
    const int t = threadIdx.x, b = blockIdx.x;
    const int i = b * 256 + t;
    const int lane = t & 31, wid = t >> 5;

    int v = (i < N_NODES) ? g_cnt[i] : 0;
    if (i < N_NODES) {
        float d = g_deg[i];
        g_dinv[i] = d > 0.0f ? rsqrtf(d) : 0.0f;
    }

    int s = v;
#pragma unroll
    for (int o = 1; o < 32; o <<= 1) {
        int u = __shfl_up_sync(0xFFFFFFFFu, s, o);
        if (lane >= o) s += u;
    }
    __shared__ int wsum[8];
    if (lane == 31) wsum[wid] = s;
    __syncthreads();
    int base = 0;
#pragma unroll
    for (int w = 0; w < 8; w++) base += (w < wid) ? wsum[w] : 0;
    if (i < N_NODES) g_off[i] = base + s - v;      // within-block exclusive
    if (t == 255) g_blksum[b] = base + s;          // block total
}

// ---------------- scan pass 2: add block bases, reset cursors ---------------
__global__ void scan2_kernel(int E) {
    const int t = threadIdx.x, b = blockIdx.x;
    __shared__ int sbase;
    if (t < 32) {
        int acc = 0;
        for (int j = t; j < b; j += 32) acc += g_blksum[j];
#pragma unroll
        for (int o = 16; o; o >>= 1) acc += __shfl_xor_sync(0xFFFFFFFFu, acc, o);
        if (t == 0) sbase = acc;
    }
    __syncthreads();
    const int i = b * 256 + t;
    if (i < N_NODES) {
        g_off[i] += sbase;
        g_cnt[i] = 0;          // reused as fill cursor
    }
    if (b == 0 && t == 0) g_off[N_NODES] = E;
}

// ---------------- CSR fill (also precomputes edge norm) ----------------
__global__ void fill_kernel(const int* __restrict__ src,
                            const int* __restrict__ dst,
                            const float* __restrict__ w, int E) {
    for (int e = blockIdx.x * blockDim.x + threadIdx.x; e < E;
         e += gridDim.x * blockDim.x) {
        int s = src[e];
        int d = dst[e];
        int pos = g_off[d] + atomicAdd(&g_cnt[d], 1);
        g_csr_src[pos] = s;
        g_csr_nrm[pos] = g_dinv[s] * w[e] * g_dinv[d];
    }
}

// ---------------- TF32 tensor-core GEMM ----------------
// C[M,256] = A[M,K] @ B[K,256] (+bias). BM=128 BN=128 BK=16, 256 thr (8 warps).
// Warp tile 64x32. Output per-matrix: fp16 (Ch) or fp32 (Cf).
template<int K>
__global__ __launch_bounds__(256)
void tf32_gemm_kernel(const float* __restrict__ A, int M, int nb,
                      const float* __restrict__ Bm1, const float* __restrict__ bias1,
                      __half* __restrict__ C1h, float* __restrict__ C1f,
                      const float* __restrict__ Bm2, const float* __restrict__ bias2,
                      __half* __restrict__ C2h, float* __restrict__ C2f) {
    __shared__ uint32_t As[128][20];
    __shared__ uint32_t Bs[16][136];

    const int tid  = threadIdx.x;
    const int lane = tid & 31;
    const int wid  = tid >> 5;
    const int wm   = (wid & 1) * 64;
    const int wn   = (wid >> 1) * 32;
    const int g    = lane >> 2;
    const int tg   = lane & 3;

    const int bm  = blockIdx.x * 128;
    const int mat = blockIdx.y / nb;
    const int bn  = (blockIdx.y % nb) * 128;

    const float* Bw   = mat ? Bm2   : Bm1;
    const float* bias = mat ? bias2 : bias1;
    __half*      Ch   = mat ? C2h   : C1h;
    float*       Cf   = mat ? C2f   : C1f;

    const int a_row = tid >> 1;
    const int a_k   = (tid & 1) * 4;
    const int b_kr  = tid >> 5;
    const int b_c   = lane * 4;
    const bool a_ok = (bm + a_row) < M;
    const long a_base = (long)(bm + a_row) * K;

    float acc[4][4][4];
#pragma unroll
    for (int mt = 0; mt < 4; mt++)
#pragma unroll
        for (int nt = 0; nt < 4; nt++)
#pragma unroll
            for (int i = 0; i < 4; i++) acc[mt][nt][i] = 0.0f;

    float4 av0 = make_float4(0.f,0.f,0.f,0.f), av1 = av0;
    if (a_ok) {
        av0 = *reinterpret_cast<const float4*>(A + a_base + a_k);
        av1 = *reinterpret_cast<const float4*>(A + a_base + a_k + 8);
    }
    float4 bv0 = *reinterpret_cast<const float4*>(Bw + (long)b_kr * D_H + bn + b_c);
    float4 bv1 = *reinterpret_cast<const float4*>(Bw + (long)(b_kr + 8) * D_H + bn + b_c);

    const int T = K / 16;
    for (int t = 0; t < T; t++) {
        __syncthreads();
        {
            uint4 pa0 = make_uint4(f2tf32(av0.x), f2tf32(av0.y), f2tf32(av0.z), f2tf32(av0.w));
            uint4 pa1 = make_uint4(f2tf32(av1.x), f2tf32(av1.y), f2tf32(av1.z), f2tf32(av1.w));
            *reinterpret_cast<uint4*>(&As[a_row][a_k])     = pa0;
            *reinterpret_cast<uint4*>(&As[a_row][a_k + 8]) = pa1;
            uint4 pb0 = make_uint4(f2tf32(bv0.x), f2tf32(bv0.y), f2tf32(bv0.z), f2tf32(bv0.w));
            uint4 pb1 = make_uint4(f2tf32(bv1.x), f2tf32(bv1.y), f2tf32(bv1.z), f2tf32(bv1.w));
            *reinterpret_cast<uint4*>(&Bs[b_kr][b_c])     = pb0;
            *reinterpret_cast<uint4*>(&Bs[b_kr + 8][b_c]) = pb1;
        }
        __syncthreads();

        if (t + 1 < T) {
            int kt = (t + 1) * 16;
            av0 = make_float4(0.f,0.f,0.f,0.f); av1 = av0;
            if (a_ok) {
                av0 = *reinterpret_cast<const float4*>(A + a_base + kt + a_k);
                av1 = *reinterpret_cast<const float4*>(A + a_base + kt + a_k + 8);
            }
            bv0 = *reinterpret_cast<const float4*>(Bw + (long)(kt + b_kr) * D_H + bn + b_c);
            bv1 = *reinterpret_cast<const float4*>(Bw + (long)(kt + b_kr + 8) * D_H + bn + b_c);
        }

#pragma unroll
        for (int ks = 0; ks < 16; ks += 8) {
            uint32_t af[4][4], bf[4][2];
#pragma unroll
            for (int mt = 0; mt < 4; mt++) {
                int r0 = wm + mt * 16 + g;
                af[mt][0] = As[r0    ][ks + tg    ];
                af[mt][1] = As[r0 + 8][ks + tg    ];
                af[mt][2] = As[r0    ][ks + tg + 4];
                af[mt][3] = As[r0 + 8][ks + tg + 4];
            }
#pragma unroll
            for (int nt = 0; nt < 4; nt++) {
                int c0 = wn + nt * 8 + g;
                bf[nt][0] = Bs[ks + tg    ][c0];
                bf[nt][1] = Bs[ks + tg + 4][c0];
            }
#pragma unroll
            for (int mt = 0; mt < 4; mt++)
#pragma unroll
                for (int nt = 0; nt < 4; nt++)
                    mma_tf32(acc[mt][nt], af[mt], bf[nt]);
        }
    }

#pragma unroll
    for (int mt = 0; mt < 4; mt++) {
        int row = bm + wm + mt * 16 + g;
#pragma unroll
        for (int nt = 0; nt < 4; nt++) {
            int col = bn + wn + nt * 8 + tg * 2;
            float b0 = bias ? bias[col]     : 0.0f;
            float b1 = bias ? bias[col + 1] : 0.0f;
            float v00 = acc[mt][nt][0] + b0, v01 = acc[mt][nt][1] + b1;
            float v10 = acc[mt][nt][2] + b0, v11 = acc[mt][nt][3] + b1;
            if (Ch) {
                if (row < M)
                    *reinterpret_cast<__half2*>(Ch + (long)row * D_H + col) =
                        __floats2half2_rn(v00, v01);
                if (row + 8 < M)
                    *reinterpret_cast<__half2*>(Ch + (long)(row + 8) * D_H + col) =
                        __floats2half2_rn(v10, v11);
            } else {
                if (row < M)
                    *reinterpret_cast<float2*>(Cf + (long)row * D_H + col) =
                        make_float2(v00, v01);
                if (row + 8 < M)
                    *reinterpret_cast<float2*>(Cf + (long)(row + 8) * D_H + col) =
                        make_float2(v10, v11);
            }
        }
    }
}

// ---------------- block-wide mean/var helper ----------------
__device__ __forceinline__ void block_stats(float t, float& mu, float& var) {
    float s = t, sq = t * t;
#pragma unroll
    for (int o = 16; o; o >>= 1) {
        s  += __shfl_xor_sync(0xFFFFFFFFu, s, o);
        sq += __shfl_xor_sync(0xFFFFFFFFu, sq, o);
    }
    __shared__ float ss[8], ssq[8];
    int wid = threadIdx.x >> 5;
    if ((threadIdx.x & 31) == 0) { ss[wid] = s; ssq[wid] = sq; }
    __syncthreads();
    float ts = 0.f, tq = 0.f;
#pragma unroll
    for (int i = 0; i < 8; i++) { ts += ss[i]; tq += ssq[i]; }
    mu = ts * (1.0f / D_H);
    var = tq * (1.0f / D_H) - mu * mu;
}

// ---------------- fused CSR gather (fp16 feat) + ReLU? + residual + LN ------
template<bool RELU>
__global__ __launch_bounds__(256)
void gather_ln_kernel(const __half* __restrict__ feat,
                      const float* __restrict__ resid,
                      const float* __restrict__ bias,
                      const float* __restrict__ gamma,
                      const float* __restrict__ beta,
                      float* __restrict__ out) {
    const int row = blockIdx.x;
    const int c = threadIdx.x;
    const long idx = (long)row * D_H + c;

    __shared__ int   s_src[64];
    __shared__ float s_nrm[64];

    const int beg = g_off[row];
    const int end = g_off[row + 1];
    const float di = g_dinv[row];

    float a0 = di * di * __half2float(feat[idx]);   // self-loop
    float a1 = 0.f, a2 = 0.f, a3 = 0.f;

    for (int chunk = beg; chunk < end; chunk += 64) {
        int n = min(64, end - chunk);
        if (chunk != beg) __syncthreads();
        if (c < n) {
            s_src[c] = g_csr_src[chunk + c];
            s_nrm[c] = g_csr_nrm[chunk + c];
        }
        __syncthreads();
        int k = 0;
        for (; k + 4 <= n; k += 4) {
            a0 += s_nrm[k    ] * __half2float(feat[(long)s_src[k    ] * D_H + c]);
            a1 += s_nrm[k + 1] * __half2float(feat[(long)s_src[k + 1] * D_H + c]);
            a2 += s_nrm[k + 2] * __half2float(feat[(long)s_src[k + 2] * D_H + c]);
            a3 += s_nrm[k + 3] * __half2float(feat[(long)s_src[k + 3] * D_H + c]);
        }
        for (; k < n; k++)
            a0 += s_nrm[k] * __half2float(feat[(long)s_src[k] * D_H + c]);
    }

    float acc = (a0 + a1) + (a2 + a3) + bias[c];
    float t = RELU ? resid[idx] + fmaxf(acc, 0.0f) : resid[idx] + acc;

    float mu, var;
    block_stats(t, mu, var);
    out[idx] = (t - mu) * rsqrtf(var + LN_EPS) * gamma[c] + beta[c];
}

// ---------------- launch ----------------
extern "C" void kernel_launch(void* const* d_in, const int* in_sizes, int n_in,
                              void* d_out, int out_size) {
    const float* x      = (const float*)d_in[0];
    const int*   ei     = (const int*)d_in[1];     // [2,E] int32
    const float* ew     = (const float*)d_in[2];
    const float* W1     = (const float*)d_in[3];
    const float* b1     = (const float*)d_in[4];
    const float* W2     = (const float*)d_in[5];
    const float* b2     = (const float*)d_in[6];
    const float* Wres   = (const float*)d_in[7];
    const float* bres   = (const float*)d_in[8];
    const float* gamma1 = (const float*)d_in[9];
    const float* beta1  = (const float*)d_in[10];
    const float* gamma2 = (const float*)d_in[11];
    const float* beta2  = (const float*)d_in[12];
    float* out = (float*)d_out;

    const int E = in_sizes[2];
    const int* src = ei;
    const int* dst = ei + E;

    __half *p_h1h = nullptr;
    float *p_hres = nullptr, *p_h = nullptr;
    cudaGetSymbolAddress((void**)&p_h1h,  g_h1h);
    cudaGetSymbolAddress((void**)&p_hres, g_hres);
    cudaGetSymbolAddress((void**)&p_h,    g_h);

    // lazily-created side stream + events (host resources only)
    static cudaStream_t sideStream = nullptr;
    static cudaEvent_t  evFork = nullptr, evJoin = nullptr;
    if (!sideStream) {
        if (cudaStreamCreateWithFlags(&sideStream, cudaStreamNonBlocking) != cudaSuccess)
            sideStream = nullptr;
        if (sideStream) {
            cudaEventCreateWithFlags(&evFork, cudaEventDisableTiming);
            cudaEventCreateWithFlags(&evJoin, cudaEventDisableTiming);
        }
    }
    cudaStream_t cs = sideStream ? sideStream : (cudaStream_t)0;

    // fork: CSR build chain on side stream
    if (sideStream) {
        cudaEventRecord(evFork, 0);
        cudaStreamWaitEvent(sideStream, evFork, 0);
    }
    init_kernel<<<80, 256, 0, cs>>>();
    degcnt_kernel<<<(E + 255) / 256, 256, 0, cs>>>(dst, ew, E);
    scan1_kernel<<<NB_SCAN, 256, 0, cs>>>();
    scan2_kernel<<<NB_SCAN, 256, 0, cs>>>(E);
    fill_kernel<<<(E + 255) / 256, 256, 0, cs>>>(src, dst, ew, E);
    if (sideStream) cudaEventRecord(evJoin, sideStream);

    const int mblk = (N_NODES + 127) / 128;   // 157
    const int nb = D_H / 128;                 // 2 col-blocks per matrix

    // main stream (concurrent with CSR build):
    // h1(fp16) = x@W1 ; hres(fp32) = x@Wres + bres
    tf32_gemm_kernel<D_IN><<<dim3(mblk, 2 * nb), 256>>>(
        x, N_NODES, nb,
        W1, nullptr, p_h1h, nullptr,
        Wres, bres, nullptr, p_hres);

    // join: gather needs both CSR and GEMM results
    if (sideStream) cudaStreamWaitEvent((cudaStream_t)0, evJoin, 0);

    // hop 0: gather(h1) + b1 + relu + hres residual + LN -> h
    gather_ln_kernel<true><<<N_NODES, D_H>>>(p_h1h, p_hres, b1, gamma1, beta1, p_h);

    // h2(fp16) = h @ W2
    tf32_gemm_kernel<D_H><<<dim3(mblk, nb), 256>>>(
        p_h, N_NODES, nb,
        W2, nullptr, p_h1h, nullptr,
        W2, nullptr, p_h1h, nullptr);

    // hop 1: gather(h2) + b2 + h residual + LN -> out
    gather_ln_kernel<false><<<N_NODES, D_H>>>(p_h1h, p_h, b2, gamma2, beta2, out);
}

// round 10
// speedup vs baseline: 2.1927x; 1.0714x over previous
#include <cuda_runtime.h>
#include <cuda_fp16.h>
#include <stdint.h>

#define N_NODES 20000
#define D_IN    128
#define D_H     256
#define LN_EPS  1e-5f
#define MAX_E   330000
#define NB_SCAN ((N_NODES + 255) / 256)   // 79

// ---------------- scratch (no dynamic allocation allowed) ----------------
__device__ float  g_deg [N_NODES];
__device__ int    g_cnt [N_NODES];
__device__ float  g_dinv[N_NODES];
__device__ int    g_off [N_NODES + 1];
__device__ int    g_blksum[NB_SCAN];
__device__ int    g_csr_src[MAX_E];
__device__ float  g_csr_nrm[MAX_E];
__device__ __half g_h1h [N_NODES * D_H];  // x@W1 (fp16), later h@W2 (fp16)
__device__ float  g_hres[N_NODES * D_H];  // x@Wres + bres
__device__ float  g_h   [N_NODES * D_H];  // after LN1

// ---------------- helpers ----------------
__device__ __forceinline__ uint32_t pack_h2(float a, float b) {
    __half2 h = __floats2half2_rn(a, b);
    return *reinterpret_cast<uint32_t*>(&h);
}

__device__ __forceinline__ void mma_f16(float* c, const uint32_t* a, const uint32_t* b) {
    asm volatile(
        "mma.sync.aligned.m16n8k16.row.col.f32.f16.f16.f32 "
        "{%0,%1,%2,%3}, {%4,%5,%6,%7}, {%8,%9}, {%0,%1,%2,%3};"
        : "+f"(c[0]), "+f"(c[1]), "+f"(c[2]), "+f"(c[3])
        : "r"(a[0]), "r"(a[1]), "r"(a[2]), "r"(a[3]), "r"(b[0]), "r"(b[1]));
}

// ---------------- init: deg = 1 (self loop), cnt = 0 ----------------
__global__ void init_kernel() {
    for (int i = blockIdx.x * blockDim.x + threadIdx.x; i < N_NODES;
         i += gridDim.x * blockDim.x) {
        g_deg[i] = 1.0f;
        g_cnt[i] = 0;
    }
}

// ---------------- degree + count accumulation over edges ----------------
__global__ void degcnt_kernel(const int* __restrict__ dst,
                              const float* __restrict__ w, int E) {
    for (int e = blockIdx.x * blockDim.x + threadIdx.x; e < E;
         e += gridDim.x * blockDim.x) {
        int d = dst[e];
        atomicAdd(&g_deg[d], w[e]);
        atomicAdd(&g_cnt[d], 1);
    }
}

// ---------------- scan pass 1: per-block exclusive scan + dinv --------------
__global__ void scan1_kernel() {
    const int t = threadIdx.x, b = blockIdx.x;
    const int i = b * 256 + t;
    const int lane = t & 31, wid = t >> 5;

    int v = (i < N_NODES) ? g_cnt[i] : 0;
    if (i < N_NODES) {
        float d = g_deg[i];
        g_dinv[i] = d > 0.0f ? rsqrtf(d) : 0.0f;
    }

    int s = v;
#pragma unroll
    for (int o = 1; o < 32; o <<= 1) {
        int u = __shfl_up_sync(0xFFFFFFFFu, s, o);
        if (lane >= o) s += u;
    }
    __shared__ int wsum[8];
    if (lane == 31) wsum[wid] = s;
    __syncthreads();
    int base = 0;
#pragma unroll
    for (int w = 0; w < 8; w++) base += (w < wid) ? wsum[w] : 0;
    if (i < N_NODES) g_off[i] = base + s - v;
    if (t == 255) g_blksum[b] = base + s;
}

// ---------------- scan pass 2: add block bases, reset cursors ---------------
__global__ void scan2_kernel(int E) {
    const int t = threadIdx.x, b = blockIdx.x;
    __shared__ int sbase;
    if (t < 32) {
        int acc = 0;
        for (int j = t; j < b; j += 32) acc += g_blksum[j];
#pragma unroll
        for (int o = 16; o; o >>= 1) acc += __shfl_xor_sync(0xFFFFFFFFu, acc, o);
        if (t == 0) sbase = acc;
    }
    __syncthreads();
    const int i = b * 256 + t;
    if (i < N_NODES) {
        g_off[i] += sbase;
        g_cnt[i] = 0;
    }
    if (b == 0 && t == 0) g_off[N_NODES] = E;
}

// ---------------- CSR fill (also precomputes edge norm) ----------------
__global__ void fill_kernel(const int* __restrict__ src,
                            const int* __restrict__ dst,
                            const float* __restrict__ w, int E) {
    for (int e = blockIdx.x * blockDim.x + threadIdx.x; e < E;
         e += gridDim.x * blockDim.x) {
        int s = src[e];
        int d = dst[e];
        int pos = g_off[d] + atomicAdd(&g_cnt[d], 1);
        g_csr_src[pos] = s;
        g_csr_nrm[pos] = g_dinv[s] * w[e] * g_dinv[d];
    }
}

// ---------------- FP16 tensor-core GEMM (fp32 in/out, fp32 accumulate) -----
// C[M,256] = A[M,K] @ B[K,256] (+bias). BM=128 BN=128 BK=16, 256 thr (8 warps).
// Warp tile 64x32; ONE m16n8k16 mma per (mt,nt) per tile.
// A smem: half2 pairs As2[m][k2], stride 12 (g*12+tg = bank permutation).
// B smem: k-pair half2 Bs2[k2][n], stride 136 (tg*8+g = bank permutation).
template<int K>
__global__ __launch_bounds__(256)
void f16_gemm_kernel(const float* __restrict__ A, int M, int nb,
                     const float* __restrict__ Bm1, const float* __restrict__ bias1,
                     __half* __restrict__ C1h, float* __restrict__ C1f,
                     const float* __restrict__ Bm2, const float* __restrict__ bias2,
                     __half* __restrict__ C2h, float* __restrict__ C2f) {
    __shared__ uint32_t As2[128][12];
    __shared__ uint32_t Bs2[8][136];

    const int tid  = threadIdx.x;
    const int lane = tid & 31;
    const int wid  = tid >> 5;
    const int wm   = (wid & 1) * 64;
    const int wn   = (wid >> 1) * 32;
    const int g    = lane >> 2;
    const int tg   = lane & 3;

    const int bm  = blockIdx.x * 128;
    const int mat = blockIdx.y / nb;
    const int bn  = (blockIdx.y % nb) * 128;

    const float* Bw   = mat ? Bm2   : Bm1;
    const float* bias = mat ? bias2 : bias1;
    __half*      Ch   = mat ? C2h   : C1h;
    float*       Cf   = mat ? C2f   : C1f;

    // A loader: 2 threads/row, 8 consecutive k each
    const int a_row = tid >> 1;          // 0..127
    const int a_k   = (tid & 1) * 8;     // 0 or 8
    const int a_k2  = a_k >> 1;          // 0 or 4
    // B loader: thread handles k-rows (2r, 2r+1), 4 cols
    const int b_r   = tid >> 5;          // 0..7
    const int b_c   = (tid & 31) * 4;    // 0..124
    const bool a_ok = (bm + a_row) < M;
    const long a_base = (long)(bm + a_row) * K;

    float acc[4][4][4];
#pragma unroll
    for (int mt = 0; mt < 4; mt++)
#pragma unroll
        for (int nt = 0; nt < 4; nt++)
#pragma unroll
            for (int i = 0; i < 4; i++) acc[mt][nt][i] = 0.0f;

    // preload tile 0
    float4 av0 = make_float4(0.f,0.f,0.f,0.f), av1 = av0;
    if (a_ok) {
        av0 = *reinterpret_cast<const float4*>(A + a_base + a_k);
        av1 = *reinterpret_cast<const float4*>(A + a_base + a_k + 4);
    }
    float4 bv0 = *reinterpret_cast<const float4*>(Bw + (long)(2 * b_r)     * D_H + bn + b_c);
    float4 bv1 = *reinterpret_cast<const float4*>(Bw + (long)(2 * b_r + 1) * D_H + bn + b_c);

    const int T = K / 16;
    for (int t = 0; t < T; t++) {
        __syncthreads();
        {
            uint2 pa0 = make_uint2(pack_h2(av0.x, av0.y), pack_h2(av0.z, av0.w));
            uint2 pa1 = make_uint2(pack_h2(av1.x, av1.y), pack_h2(av1.z, av1.w));
            *reinterpret_cast<uint2*>(&As2[a_row][a_k2])     = pa0;
            *reinterpret_cast<uint2*>(&As2[a_row][a_k2 + 2]) = pa1;
            uint4 pb = make_uint4(pack_h2(bv0.x, bv1.x), pack_h2(bv0.y, bv1.y),
                                  pack_h2(bv0.z, bv1.z), pack_h2(bv0.w, bv1.w));
            *reinterpret_cast<uint4*>(&Bs2[b_r][b_c]) = pb;
        }
        __syncthreads();

        if (t + 1 < T) {   // prefetch next tile (overlaps mma block)
            int kt = (t + 1) * 16;
            av0 = make_float4(0.f,0.f,0.f,0.f); av1 = av0;
            if (a_ok) {
                av0 = *reinterpret_cast<const float4*>(A + a_base + kt + a_k);
                av1 = *reinterpret_cast<const float4*>(A + a_base + kt + a_k + 4);
            }
            bv0 = *reinterpret_cast<const float4*>(Bw + (long)(kt + 2 * b_r)     * D_H + bn + b_c);
            bv1 = *reinterpret_cast<const float4*>(Bw + (long)(kt + 2 * b_r + 1) * D_H + bn + b_c);
        }

        uint32_t af[4][4], bf[4][2];
#pragma unroll
        for (int mt = 0; mt < 4; mt++) {
            int r0 = wm + mt * 16 + g;
            af[mt][0] = As2[r0    ][tg    ];
            af[mt][1] = As2[r0 + 8][tg    ];
            af[mt][2] = As2[r0    ][tg + 4];
            af[mt][3] = As2[r0 + 8][tg + 4];
        }
#pragma unroll
        for (int nt = 0; nt < 4; nt++) {
            int c0 = wn + nt * 8 + g;
            bf[nt][0] = Bs2[tg    ][c0];
            bf[nt][1] = Bs2[tg + 4][c0];
        }
#pragma unroll
        for (int mt = 0; mt < 4; mt++)
#pragma unroll
            for (int nt = 0; nt < 4; nt++)
                mma_f16(acc[mt][nt], af[mt], bf[nt]);
    }

#pragma unroll
    for (int mt = 0; mt < 4; mt++) {
        int row = bm + wm + mt * 16 + g;
#pragma unroll
        for (int nt = 0; nt < 4; nt++) {
            int col = bn + wn + nt * 8 + tg * 2;
            float b0 = bias ? bias[col]     : 0.0f;
            float b1 = bias ? bias[col + 1] : 0.0f;
            float v00 = acc[mt][nt][0] + b0, v01 = acc[mt][nt][1] + b1;
            float v10 = acc[mt][nt][2] + b0, v11 = acc[mt][nt][3] + b1;
            if (Ch) {
                if (row < M)
                    *reinterpret_cast<__half2*>(Ch + (long)row * D_H + col) =
                        __floats2half2_rn(v00, v01);
                if (row + 8 < M)
                    *reinterpret_cast<__half2*>(Ch + (long)(row + 8) * D_H + col) =
                        __floats2half2_rn(v10, v11);
            } else {
                if (row < M)
                    *reinterpret_cast<float2*>(Cf + (long)row * D_H + col) =
                        make_float2(v00, v01);
                if (row + 8 < M)
                    *reinterpret_cast<float2*>(Cf + (long)(row + 8) * D_H + col) =
                        make_float2(v10, v11);
            }
        }
    }
}

// ---------------- block-wide mean/var helper ----------------
__device__ __forceinline__ void block_stats(float t, float& mu, float& var) {
    float s = t, sq = t * t;
#pragma unroll
    for (int o = 16; o; o >>= 1) {
        s  += __shfl_xor_sync(0xFFFFFFFFu, s, o);
        sq += __shfl_xor_sync(0xFFFFFFFFu, sq, o);
    }
    __shared__ float ss[8], ssq[8];
    int wid = threadIdx.x >> 5;
    if ((threadIdx.x & 31) == 0) { ss[wid] = s; ssq[wid] = sq; }
    __syncthreads();
    float ts = 0.f, tq = 0.f;
#pragma unroll
    for (int i = 0; i < 8; i++) { ts += ss[i]; tq += ssq[i]; }
    mu = ts * (1.0f / D_H);
    var = tq * (1.0f / D_H) - mu * mu;
}

// ---------------- fused CSR gather (fp16 feat) + ReLU? + residual + LN ------
template<bool RELU>
__global__ __launch_bounds__(256)
void gather_ln_kernel(const __half* __restrict__ feat,
                      const float* __restrict__ resid,
                      const float* __restrict__ bias,
                      const float* __restrict__ gamma,
                      const float* __restrict__ beta,
                      float* __restrict__ out) {
    const int row = blockIdx.x;
    const int c = threadIdx.x;
    const long idx = (long)row * D_H + c;

    __shared__ int   s_src[64];
    __shared__ float s_nrm[64];

    const int beg = g_off[row];
    const int end = g_off[row + 1];
    const float di = g_dinv[row];

    float a0 = di * di * __half2float(feat[idx]);   // self-loop
    float a1 = 0.f, a2 = 0.f, a3 = 0.f;

    for (int chunk = beg; chunk < end; chunk += 64) {
        int n = min(64, end - chunk);
        if (chunk != beg) __syncthreads();
        if (c < n) {
            s_src[c] = g_csr_src[chunk + c];
            s_nrm[c] = g_csr_nrm[chunk + c];
        }
        __syncthreads();
        int k = 0;
        for (; k + 4 <= n; k += 4) {
            a0 += s_nrm[k    ] * __half2float(feat[(long)s_src[k    ] * D_H + c]);
            a1 += s_nrm[k + 1] * __half2float(feat[(long)s_src[k + 1] * D_H + c]);
            a2 += s_nrm[k + 2] * __half2float(feat[(long)s_src[k + 2] * D_H + c]);
            a3 += s_nrm[k + 3] * __half2float(feat[(long)s_src[k + 3] * D_H + c]);
        }
        for (; k < n; k++)
            a0 += s_nrm[k] * __half2float(feat[(long)s_src[k] * D_H + c]);
    }

    float acc = (a0 + a1) + (a2 + a3) + bias[c];
    float t = RELU ? resid[idx] + fmaxf(acc, 0.0f) : resid[idx] + acc;

    float mu, var;
    block_stats(t, mu, var);
    out[idx] = (t - mu) * rsqrtf(var + LN_EPS) * gamma[c] + beta[c];
}

// ---------------- launch ----------------
extern "C" void kernel_launch(void* const* d_in, const int* in_sizes, int n_in,
                              void* d_out, int out_size) {
    const float* x      = (const float*)d_in[0];
    const int*   ei     = (const int*)d_in[1];     // [2,E] int32
    const float* ew     = (const float*)d_in[2];
    const float* W1     = (const float*)d_in[3];
    const float* b1     = (const float*)d_in[4];
    const float* W2     = (const float*)d_in[5];
    const float* b2     = (const float*)d_in[6];
    const float* Wres   = (const float*)d_in[7];
    const float* bres   = (const float*)d_in[8];
    const float* gamma1 = (const float*)d_in[9];
    const float* beta1  = (const float*)d_in[10];
    const float* gamma2 = (const float*)d_in[11];
    const float* beta2  = (const float*)d_in[12];
    float* out = (float*)d_out;

    const int E = in_sizes[2];
    const int* src = ei;
    const int* dst = ei + E;

    __half *p_h1h = nullptr;
    float *p_hres = nullptr, *p_h = nullptr;
    cudaGetSymbolAddress((void**)&p_h1h,  g_h1h);
    cudaGetSymbolAddress((void**)&p_hres, g_hres);
    cudaGetSymbolAddress((void**)&p_h,    g_h);

    // lazily-created side stream + events (host resources only)
    static cudaStream_t sideStream = nullptr;
    static cudaEvent_t  evFork = nullptr, evJoin = nullptr;
    if (!sideStream) {
        if (cudaStreamCreateWithFlags(&sideStream, cudaStreamNonBlocking) != cudaSuccess)
            sideStream = nullptr;
        if (sideStream) {
            cudaEventCreateWithFlags(&evFork, cudaEventDisableTiming);
            cudaEventCreateWithFlags(&evJoin, cudaEventDisableTiming);
        }
    }
    cudaStream_t cs = sideStream ? sideStream : (cudaStream_t)0;

    // fork: CSR build chain on side stream
    if (sideStream) {
        cudaEventRecord(evFork, 0);
        cudaStreamWaitEvent(sideStream, evFork, 0);
    }
    init_kernel<<<80, 256, 0, cs>>>();
    degcnt_kernel<<<(E + 255) / 256, 256, 0, cs>>>(dst, ew, E);
    scan1_kernel<<<NB_SCAN, 256, 0, cs>>>();
    scan2_kernel<<<NB_SCAN, 256, 0, cs>>>(E);
    fill_kernel<<<(E + 255) / 256, 256, 0, cs>>>(src, dst, ew, E);
    if (sideStream) cudaEventRecord(evJoin, sideStream);

    const int mblk = (N_NODES + 127) / 128;   // 157
    const int nb = D_H / 128;                 // 2 col-blocks per matrix

    // main stream (concurrent with CSR build):
    // h1(fp16) = x@W1 ; hres(fp32) = x@Wres + bres
    f16_gemm_kernel<D_IN><<<dim3(mblk, 2 * nb), 256>>>(
        x, N_NODES, nb,
        W1, nullptr, p_h1h, nullptr,
        Wres, bres, nullptr, p_hres);

    // join: gather needs both CSR and GEMM results
    if (sideStream) cudaStreamWaitEvent((cudaStream_t)0, evJoin, 0);

    // hop 0: gather(h1) + b1 + relu + hres residual + LN -> h
    gather_ln_kernel<true><<<N_NODES, D_H>>>(p_h1h, p_hres, b1, gamma1, beta1, p_h);

    // h2(fp16) = h @ W2
    f16_gemm_kernel<D_H><<<dim3(mblk, nb), 256>>>(
        p_h, N_NODES, nb,
        W2, nullptr, p_h1h, nullptr,
        W2, nullptr, p_h1h, nullptr);

    // hop 1: gather(h2) + b2 + h residual + LN -> out
    gather_ln_kernel<false><<<N_NODES, D_H>>>(p_h1h, p_h, b2, gamma2, beta2, out);
}

// round 11
// speedup vs baseline: 2.2777x; 1.0388x over previous
#include <cuda_runtime.h>
#include <cuda_fp16.h>
#include <stdint.h>

#define N_NODES 20000
#define D_IN    128
#define D_H     256
#define D_H2    128               // half2 columns
#define LN_EPS  1e-5f
#define MAX_E   330000
#define NB_SCAN ((N_NODES + 255) / 256)   // 79

// ---------------- scratch (no dynamic allocation allowed) ----------------
__device__ float  g_deg [N_NODES];
__device__ int    g_cnt [N_NODES];
__device__ float  g_dinv[N_NODES];
__device__ int    g_off [N_NODES + 1];
__device__ int    g_blksum[NB_SCAN];
__device__ int    g_csr_src[MAX_E];
__device__ float  g_csr_nrm[MAX_E];
__device__ __half g_h1h [N_NODES * D_H];  // x@W1 (fp16), later h@W2 (fp16)
__device__ float  g_hres[N_NODES * D_H];  // x@Wres + bres
__device__ float  g_h   [N_NODES * D_H];  // after LN1

// ---------------- helpers ----------------
__device__ __forceinline__ uint32_t pack_h2(float a, float b) {
    __half2 h = __floats2half2_rn(a, b);
    return *reinterpret_cast<uint32_t*>(&h);
}

__device__ __forceinline__ void mma_f16(float* c, const uint32_t* a, const uint32_t* b) {
    asm volatile(
        "mma.sync.aligned.m16n8k16.row.col.f32.f16.f16.f32 "
        "{%0,%1,%2,%3}, {%4,%5,%6,%7}, {%8,%9}, {%0,%1,%2,%3};"
        : "+f"(c[0]), "+f"(c[1]), "+f"(c[2]), "+f"(c[3])
        : "r"(a[0]), "r"(a[1]), "r"(a[2]), "r"(a[3]), "r"(b[0]), "r"(b[1]));
}

// ---------------- init: deg = 1 (self loop), cnt = 0 ----------------
__global__ void init_kernel() {
    for (int i = blockIdx.x * blockDim.x + threadIdx.x; i < N_NODES;
         i += gridDim.x * blockDim.x) {
        g_deg[i] = 1.0f;
        g_cnt[i] = 0;
    }
}

// ---------------- degree + count accumulation over edges ----------------
__global__ void degcnt_kernel(const int* __restrict__ dst,
                              const float* __restrict__ w, int E) {
    for (int e = blockIdx.x * blockDim.x + threadIdx.x; e < E;
         e += gridDim.x * blockDim.x) {
        int d = dst[e];
        atomicAdd(&g_deg[d], w[e]);
        atomicAdd(&g_cnt[d], 1);
    }
}

// ---------------- scan pass 1: per-block exclusive scan + dinv --------------
__global__ void scan1_kernel() {
    const int t = threadIdx.x, b = blockIdx.x;
    const int i = b * 256 + t;
    const int lane = t & 31, wid = t >> 5;

    int v = (i < N_NODES) ? g_cnt[i] : 0;
    if (i < N_NODES) {
        float d = g_deg[i];
        g_dinv[i] = d > 0.0f ? rsqrtf(d) : 0.0f;
    }

    int s = v;
#pragma unroll
    for (int o = 1; o < 32; o <<= 1) {
        int u = __shfl_up_sync(0xFFFFFFFFu, s, o);
        if (lane >= o) s += u;
    }
    __shared__ int wsum[8];
    if (lane == 31) wsum[wid] = s;
    __syncthreads();
    int base = 0;
#pragma unroll
    for (int w = 0; w < 8; w++) base += (w < wid) ? wsum[w] : 0;
    if (i < N_NODES) g_off[i] = base + s - v;
    if (t == 255) g_blksum[b] = base + s;
}

// ---------------- scan pass 2: add block bases, reset cursors ---------------
__global__ void scan2_kernel(int E) {
    const int t = threadIdx.x, b = blockIdx.x;
    __shared__ int sbase;
    if (t < 32) {
        int acc = 0;
        for (int j = t; j < b; j += 32) acc += g_blksum[j];
#pragma unroll
        for (int o = 16; o; o >>= 1) acc += __shfl_xor_sync(0xFFFFFFFFu, acc, o);
        if (t == 0) sbase = acc;
    }
    __syncthreads();
    const int i = b * 256 + t;
    if (i < N_NODES) {
        g_off[i] += sbase;
        g_cnt[i] = 0;
    }
    if (b == 0 && t == 0) g_off[N_NODES] = E;
}

// ---------------- CSR fill (also precomputes edge norm) ----------------
__global__ void fill_kernel(const int* __restrict__ src,
                            const int* __restrict__ dst,
                            const float* __restrict__ w, int E) {
    for (int e = blockIdx.x * blockDim.x + threadIdx.x; e < E;
         e += gridDim.x * blockDim.x) {
        int s = src[e];
        int d = dst[e];
        int pos = g_off[d] + atomicAdd(&g_cnt[d], 1);
        g_csr_src[pos] = s;
        g_csr_nrm[pos] = g_dinv[s] * w[e] * g_dinv[d];
    }
}

// ---------------- FP16 tensor-core GEMM (fp32 in/out, fp32 accumulate) -----
template<int K>
__global__ __launch_bounds__(256)
void f16_gemm_kernel(const float* __restrict__ A, int M, int nb,
                     const float* __restrict__ Bm1, const float* __restrict__ bias1,
                     __half* __restrict__ C1h, float* __restrict__ C1f,
                     const float* __restrict__ Bm2, const float* __restrict__ bias2,
                     __half* __restrict__ C2h, float* __restrict__ C2f) {
    __shared__ uint32_t As2[128][12];
    __shared__ uint32_t Bs2[8][136];

    const int tid  = threadIdx.x;
    const int lane = tid & 31;
    const int wid  = tid >> 5;
    const int wm   = (wid & 1) * 64;
    const int wn   = (wid >> 1) * 32;
    const int g    = lane >> 2;
    const int tg   = lane & 3;

    const int bm  = blockIdx.x * 128;
    const int mat = blockIdx.y / nb;
    const int bn  = (blockIdx.y % nb) * 128;

    const float* Bw   = mat ? Bm2   : Bm1;
    const float* bias = mat ? bias2 : bias1;
    __half*      Ch   = mat ? C2h   : C1h;
    float*       Cf   = mat ? C2f   : C1f;

    const int a_row = tid >> 1;
    const int a_k   = (tid & 1) * 8;
    const int a_k2  = a_k >> 1;
    const int b_r   = tid >> 5;
    const int b_c   = (tid & 31) * 4;
    const bool a_ok = (bm + a_row) < M;
    const long a_base = (long)(bm + a_row) * K;

    float acc[4][4][4];
#pragma unroll
    for (int mt = 0; mt < 4; mt++)
#pragma unroll
        for (int nt = 0; nt < 4; nt++)
#pragma unroll
            for (int i = 0; i < 4; i++) acc[mt][nt][i] = 0.0f;

    float4 av0 = make_float4(0.f,0.f,0.f,0.f), av1 = av0;
    if (a_ok) {
        av0 = *reinterpret_cast<const float4*>(A + a_base + a_k);
        av1 = *reinterpret_cast<const float4*>(A + a_base + a_k + 4);
    }
    float4 bv0 = *reinterpret_cast<const float4*>(Bw + (long)(2 * b_r)     * D_H + bn + b_c);
    float4 bv1 = *reinterpret_cast<const float4*>(Bw + (long)(2 * b_r + 1) * D_H + bn + b_c);

    const int T = K / 16;
    for (int t = 0; t < T; t++) {
        __syncthreads();
        {
            uint2 pa0 = make_uint2(pack_h2(av0.x, av0.y), pack_h2(av0.z, av0.w));
            uint2 pa1 = make_uint2(pack_h2(av1.x, av1.y), pack_h2(av1.z, av1.w));
            *reinterpret_cast<uint2*>(&As2[a_row][a_k2])     = pa0;
            *reinterpret_cast<uint2*>(&As2[a_row][a_k2 + 2]) = pa1;
            uint4 pb = make_uint4(pack_h2(bv0.x, bv1.x), pack_h2(bv0.y, bv1.y),
                                  pack_h2(bv0.z, bv1.z), pack_h2(bv0.w, bv1.w));
            *reinterpret_cast<uint4*>(&Bs2[b_r][b_c]) = pb;
        }
        __syncthreads();

        if (t + 1 < T) {
            int kt = (t + 1) * 16;
            av0 = make_float4(0.f,0.f,0.f,0.f); av1 = av0;
            if (a_ok) {
                av0 = *reinterpret_cast<const float4*>(A + a_base + kt + a_k);
                av1 = *reinterpret_cast<const float4*>(A + a_base + kt + a_k + 4);
            }
            bv0 = *reinterpret_cast<const float4*>(Bw + (long)(kt + 2 * b_r)     * D_H + bn + b_c);
            bv1 = *reinterpret_cast<const float4*>(Bw + (long)(kt + 2 * b_r + 1) * D_H + bn + b_c);
        }

        uint32_t af[4][4], bf[4][2];
#pragma unroll
        for (int mt = 0; mt < 4; mt++) {
            int r0 = wm + mt * 16 + g;
            af[mt][0] = As2[r0    ][tg    ];
            af[mt][1] = As2[r0 + 8][tg    ];
            af[mt][2] = As2[r0    ][tg + 4];
            af[mt][3] = As2[r0 + 8][tg + 4];
        }
#pragma unroll
        for (int nt = 0; nt < 4; nt++) {
            int c0 = wn + nt * 8 + g;
            bf[nt][0] = Bs2[tg    ][c0];
            bf[nt][1] = Bs2[tg + 4][c0];
        }
#pragma unroll
        for (int mt = 0; mt < 4; mt++)
#pragma unroll
            for (int nt = 0; nt < 4; nt++)
                mma_f16(acc[mt][nt], af[mt], bf[nt]);
    }

#pragma unroll
    for (int mt = 0; mt < 4; mt++) {
        int row = bm + wm + mt * 16 + g;
#pragma unroll
        for (int nt = 0; nt < 4; nt++) {
            int col = bn + wn + nt * 8 + tg * 2;
            float b0 = bias ? bias[col]     : 0.0f;
            float b1 = bias ? bias[col + 1] : 0.0f;
            float v00 = acc[mt][nt][0] + b0, v01 = acc[mt][nt][1] + b1;
            float v10 = acc[mt][nt][2] + b0, v11 = acc[mt][nt][3] + b1;
            if (Ch) {
                if (row < M)
                    *reinterpret_cast<__half2*>(Ch + (long)row * D_H + col) =
                        __floats2half2_rn(v00, v01);
                if (row + 8 < M)
                    *reinterpret_cast<__half2*>(Ch + (long)(row + 8) * D_H + col) =
                        __floats2half2_rn(v10, v11);
            } else {
                if (row < M)
                    *reinterpret_cast<float2*>(Cf + (long)row * D_H + col) =
                        make_float2(v00, v01);
                if (row + 8 < M)
                    *reinterpret_cast<float2*>(Cf + (long)(row + 8) * D_H + col) =
                        make_float2(v10, v11);
            }
        }
    }
}

// ---------------- fused CSR gather (half2, split-edge) + ReLU? + res + LN ---
// 256 threads = 128 half2 columns x 2 edge-parity groups. Each parity group
// covers half the row's edges with 4 accumulators -> ~2 dependent L2 rounds.
template<bool RELU>
__global__ __launch_bounds__(256)
void gather_ln_kernel(const __half* __restrict__ feat,
                      const float* __restrict__ resid,
                      const float* __restrict__ bias,
                      const float* __restrict__ gamma,
                      const float* __restrict__ beta,
                      float* __restrict__ out) {
    const int row = blockIdx.x;
    const int tid = threadIdx.x;
    const int c2  = tid & 127;        // half2 column
    const int par = tid >> 7;         // edge parity 0/1
    const __half2* f2 = reinterpret_cast<const __half2*>(feat);
    const long idx2 = (long)row * D_H2 + c2;

    __shared__ int    s_src[64];
    __shared__ float  s_nrm[64];
    __shared__ float2 s_par[128];

    const int beg = g_off[row];
    const int end = g_off[row + 1];
    const float di = g_dinv[row];

    float2 a0 = make_float2(0.f, 0.f), a1 = a0, a2 = a0, a3 = a0;
    if (par == 0) {   // self-loop
        float2 v = __half22float2(f2[idx2]);
        a0.x = di * di * v.x;
        a0.y = di * di * v.y;
    }

    for (int chunk = beg; chunk < end; chunk += 64) {
        int n = min(64, end - chunk);
        if (chunk != beg) __syncthreads();
        if (tid < n) {
            s_src[tid] = g_csr_src[chunk + tid];
            s_nrm[tid] = g_csr_nrm[chunk + tid];
        }
        __syncthreads();
        int k = par;
        for (; k + 6 < n; k += 8) {
            float2 v0 = __half22float2(f2[(long)s_src[k    ] * D_H2 + c2]);
            float2 v1 = __half22float2(f2[(long)s_src[k + 2] * D_H2 + c2]);
            float2 v2 = __half22float2(f2[(long)s_src[k + 4] * D_H2 + c2]);
            float2 v3 = __half22float2(f2[(long)s_src[k + 6] * D_H2 + c2]);
            float n0 = s_nrm[k], n1 = s_nrm[k + 2], n2 = s_nrm[k + 4], n3 = s_nrm[k + 6];
            a0.x += n0 * v0.x; a0.y += n0 * v0.y;
            a1.x += n1 * v1.x; a1.y += n1 * v1.y;
            a2.x += n2 * v2.x; a2.y += n2 * v2.y;
            a3.x += n3 * v3.x; a3.y += n3 * v3.y;
        }
        for (; k < n; k += 2) {
            float2 v = __half22float2(f2[(long)s_src[k] * D_H2 + c2]);
            float nn = s_nrm[k];
            a0.x += nn * v.x; a0.y += nn * v.y;
        }
    }

    float2 acc = make_float2((a0.x + a1.x) + (a2.x + a3.x),
                             (a0.y + a1.y) + (a2.y + a3.y));

    // combine the two parity groups
    __syncthreads();
    if (par == 1) s_par[c2] = acc;
    __syncthreads();

    float2 t2 = make_float2(0.f, 0.f);
    if (par == 0) {
        float2 o = s_par[c2];
        acc.x += o.x; acc.y += o.y;
        int col = c2 * 2;
        float bx = bias[col], by = bias[col + 1];
        float2 r = *reinterpret_cast<const float2*>(resid + (long)row * D_H + col);
        if (RELU) {
            t2.x = r.x + fmaxf(acc.x + bx, 0.0f);
            t2.y = r.y + fmaxf(acc.y + by, 0.0f);
        } else {
            t2.x = r.x + acc.x + bx;
            t2.y = r.y + acc.y + by;
        }
    }

    // LN stats over 256 values (par-1 threads contribute 0)
    float s = t2.x + t2.y, sq = t2.x * t2.x + t2.y * t2.y;
#pragma unroll
    for (int o = 16; o; o >>= 1) {
        s  += __shfl_xor_sync(0xFFFFFFFFu, s, o);
        sq += __shfl_xor_sync(0xFFFFFFFFu, sq, o);
    }
    __shared__ float ss[8], ssq[8];
    int wid = tid >> 5;
    if ((tid & 31) == 0) { ss[wid] = s; ssq[wid] = sq; }
    __syncthreads();
    float ts = 0.f, tq = 0.f;
#pragma unroll
    for (int i = 0; i < 8; i++) { ts += ss[i]; tq += ssq[i]; }
    float mu  = ts * (1.0f / D_H);
    float var = tq * (1.0f / D_H) - mu * mu;

    if (par == 0) {
        float rstd = rsqrtf(var + LN_EPS);
        int col = c2 * 2;
        float2 o;
        o.x = (t2.x - mu) * rstd * gamma[col]     + beta[col];
        o.y = (t2.y - mu) * rstd * gamma[col + 1] + beta[col + 1];
        *reinterpret_cast<float2*>(out + (long)row * D_H + col) = o;
    }
}

// ---------------- launch ----------------
extern "C" void kernel_launch(void* const* d_in, const int* in_sizes, int n_in,
                              void* d_out, int out_size) {
    const float* x      = (const float*)d_in[0];
    const int*   ei     = (const int*)d_in[1];     // [2,E] int32
    const float* ew     = (const float*)d_in[2];
    const float* W1     = (const float*)d_in[3];
    const float* b1     = (const float*)d_in[4];
    const float* W2     = (const float*)d_in[5];
    const float* b2     = (const float*)d_in[6];
    const float* Wres   = (const float*)d_in[7];
    const float* bres   = (const float*)d_in[8];
    const float* gamma1 = (const float*)d_in[9];
    const float* beta1  = (const float*)d_in[10];
    const float* gamma2 = (const float*)d_in[11];
    const float* beta2  = (const float*)d_in[12];
    float* out = (float*)d_out;

    const int E = in_sizes[2];
    const int* src = ei;
    const int* dst = ei + E;

    __half *p_h1h = nullptr;
    float *p_hres = nullptr, *p_h = nullptr;
    cudaGetSymbolAddress((void**)&p_h1h,  g_h1h);
    cudaGetSymbolAddress((void**)&p_hres, g_hres);
    cudaGetSymbolAddress((void**)&p_h,    g_h);

    // lazily-created side stream + events (host resources only)
    static cudaStream_t sideStream = nullptr;
    static cudaEvent_t  evFork = nullptr, evJoin = nullptr;
    if (!sideStream) {
        if (cudaStreamCreateWithFlags(&sideStream, cudaStreamNonBlocking) != cudaSuccess)
            sideStream = nullptr;
        if (sideStream) {
            cudaEventCreateWithFlags(&evFork, cudaEventDisableTiming);
            cudaEventCreateWithFlags(&evJoin, cudaEventDisableTiming);
        }
    }
    cudaStream_t cs = sideStream ? sideStream : (cudaStream_t)0;

    // fork: CSR build chain on side stream
    if (sideStream) {
        cudaEventRecord(evFork, 0);
        cudaStreamWaitEvent(sideStream, evFork, 0);
    }
    init_kernel<<<80, 256, 0, cs>>>();
    degcnt_kernel<<<(E + 255) / 256, 256, 0, cs>>>(dst, ew, E);
    scan1_kernel<<<NB_SCAN, 256, 0, cs>>>();
    scan2_kernel<<<NB_SCAN, 256, 0, cs>>>(E);
    fill_kernel<<<(E + 255) / 256, 256, 0, cs>>>(src, dst, ew, E);
    if (sideStream) cudaEventRecord(evJoin, sideStream);

    const int mblk = (N_NODES + 127) / 128;   // 157
    const int nb = D_H / 128;                 // 2 col-blocks per matrix

    // main stream (concurrent with CSR build):
    // h1(fp16) = x@W1 ; hres(fp32) = x@Wres + bres
    f16_gemm_kernel<D_IN><<<dim3(mblk, 2 * nb), 256>>>(
        x, N_NODES, nb,
        W1, nullptr, p_h1h, nullptr,
        Wres, bres, nullptr, p_hres);

    // join: gather needs both CSR and GEMM results
    if (sideStream) cudaStreamWaitEvent((cudaStream_t)0, evJoin, 0);

    // hop 0: gather(h1) + b1 + relu + hres residual + LN -> h
    gather_ln_kernel<true><<<N_NODES, 256>>>(p_h1h, p_hres, b1, gamma1, beta1, p_h);

    // h2(fp16) = h @ W2
    f16_gemm_kernel<D_H><<<dim3(mblk, nb), 256>>>(
        p_h, N_NODES, nb,
        W2, nullptr, p_h1h, nullptr,
        W2, nullptr, p_h1h, nullptr);

    // hop 1: gather(h2) + b2 + h residual + LN -> out
    gather_ln_kernel<false><<<N_NODES, 256>>>(p_h1h, p_h, b2, gamma2, beta2, out);
}